// round 13
// baseline (speedup 1.0000x reference)
#include <cuda_runtime.h>
#include <cuda_bf16.h>
#include <mma.h>
#include <math.h>
#include <stdint.h>

using namespace nvcuda;

// ---------------- problem constants ----------------
#define TOK   32768            // B*H*W
#define EDIM  384
#define D1    768
#define BSZ   8
#define NSP   64               // H = W = 64
#define RPEW  512
#define RP_SL 98304            // 128*768 floats per k-slice
#define RP_NET (4 * RP_SL)     // per-net partial block

// ---------------- device scratch (allocation-free) ----------------
__device__ __align__(256) __nv_bfloat16 g_xnb[(size_t)TOK * EDIM];   // normed x, bf16
__device__ __align__(256) __nv_bfloat16 g_ut [(size_t)D1 * TOK];     // u transposed [c][tok]
__device__ __align__(256) __nv_bfloat16 g_vt [(size_t)D1 * TOK];     // v transposed [c][tok]
__device__ __align__(256) __nv_bfloat16 g_gt [(size_t)D1 * TOK];     // g = u*tno, [c][tok]
__device__ __align__(256) __nv_bfloat16 g_wub[EDIM * D1];            // Wu [k][n]
__device__ __align__(256) __nv_bfloat16 g_wvb[EDIM * D1];            // Wv [k][n]
__device__ __align__(256) __nv_bfloat16 g_wob[D1 * EDIM];            // Wo [k][n]
__device__ __align__(256) float         g_at1[D1 * 128];             // W-axis coeffs [c][lag]
__device__ __align__(256) float         g_at2[D1 * 128];             // H-axis coeffs [c][lag]
__device__ __align__(256) float         g_rP [2 * 4 * 128 * 768];    // split-K partials
__device__ __align__(256) float         g_rB [2 * 128 * RPEW];       // rpe normalized
__device__ __align__(256) __nv_bfloat16 g_T2b [(size_t)D1 * 64 * 64]; // T2[c][i][k]
__device__ __align__(256) __nv_bfloat16 g_T1tb[(size_t)D1 * 64 * 64]; // T1t[c][k][j]

// ---------------- cp.async helpers ----------------
__device__ __forceinline__ void cpa16(void* dst, const void* src) {
    unsigned int s = (unsigned int)__cvta_generic_to_shared(dst);
    asm volatile("cp.async.cg.shared.global [%0], [%1], 16;\n" :: "r"(s), "l"(src));
}
#define CP_COMMIT()  asm volatile("cp.async.commit_group;\n" ::: "memory")
#define CP_WAIT0()   asm volatile("cp.async.wait_group 0;\n" ::: "memory")
#define CP_WAIT1()   asm volatile("cp.async.wait_group 1;\n" ::: "memory")

__device__ __forceinline__ float silu_fast(float v) {
    float th;
    asm("tanh.approx.f32 %0, %1;" : "=f"(th) : "f"(v * 0.5f));
    return 0.5f * v + 0.5f * v * th;             // v * sigmoid(v)
}

// ---------------- mega prep: norm | weight cvt | rpe layer-0 norm ------------
// blocks [0,4096): srms(x) -> g_xnb ; [4096,5248): cvt ; [5248,5280): rpe X0
__global__ void mega_prep(const float* __restrict__ x,
                          const float* __restrict__ wu, const float* __restrict__ wv,
                          const float* __restrict__ wo,
                          const float* __restrict__ pw1, const float* __restrict__ pb1,
                          const float* __restrict__ pw2, const float* __restrict__ pb2) {
    int bid = blockIdx.x;
    int tid = threadIdx.x;
    if (bid < 4096) {                            // ---- SimpleRMSNorm ----
        int w    = (bid * 256 + tid) >> 5;
        int lane = tid & 31;
        const float* xr = x + (size_t)w * EDIM;
        float v[12], s = 0.f;
#pragma unroll
        for (int i = 0; i < 12; i++) { v[i] = xr[lane + 32 * i]; s += v[i] * v[i]; }
#pragma unroll
        for (int o = 16; o; o >>= 1) s += __shfl_xor_sync(0xffffffffu, s, o);
        float r = rsqrtf(s / (float)EDIM + 1e-6f);
        __nv_bfloat16* o = g_xnb + (size_t)w * EDIM;
#pragma unroll
        for (int i = 0; i < 12; i++) o[lane + 32 * i] = __float2bfloat16(v[i] * r);
    } else if (bid < 5248) {                     // ---- weight convert ----
        int i = (bid - 4096) * 256 + tid;
        if (i < EDIM * D1) {
            g_wub[i] = __float2bfloat16(wu[i]);
            g_wvb[i] = __float2bfloat16(wv[i]);
            g_wob[i] = __float2bfloat16(wo[i]);
        }
    } else {                                     // ---- rpe X0 = relu(srms(relu(p*pw+pb)))
        int wid = tid >> 5, lane = tid & 31;
        int g = (bid - 5248) * 8 + wid;          // 0..255
        int net = g >> 7, r = g & 127;
        const float* pw = net ? pw2 : pw1;
        const float* pb = net ? pb2 : pb1;
        float p = (r == 0 || r == 64) ? 0.f : (r < 64 ? (float)r : (float)(r - 128));
        float4 v[4];
#pragma unroll
        for (int i = 0; i < 4; i++) {
            float4 w4 = ((const float4*)pw)[lane + 32 * i];
            float4 b4 = ((const float4*)pb)[lane + 32 * i];
            v[i].x = fmaxf(p * w4.x + b4.x, 0.f);
            v[i].y = fmaxf(p * w4.y + b4.y, 0.f);
            v[i].z = fmaxf(p * w4.z + b4.z, 0.f);
            v[i].w = fmaxf(p * w4.w + b4.w, 0.f);
        }
        float ss = 0.f;
#pragma unroll
        for (int i = 0; i < 4; i++)
            ss += v[i].x * v[i].x + v[i].y * v[i].y + v[i].z * v[i].z + v[i].w * v[i].w;
#pragma unroll
        for (int o = 16; o; o >>= 1) ss += __shfl_xor_sync(0xffffffffu, ss, o);
        float rs = rsqrtf(ss / (float)RPEW + 1e-6f);
        float* Xo = g_rB + (size_t)net * 128 * RPEW + (size_t)r * RPEW;
#pragma unroll
        for (int i = 0; i < 4; i++) {
            float4 o4;
            o4.x = fmaxf(v[i].x * rs, 0.f); o4.y = fmaxf(v[i].y * rs, 0.f);
            o4.z = fmaxf(v[i].z * rs, 0.f); o4.w = fmaxf(v[i].w * rs, 0.f);
            ((float4*)Xo)[lane + 32 * i] = o4;
        }
    }
}

// ---------------- GEMM: u/v = silu(xn @ W + b), 128x128 tile, 3-stage 1-sync --
#define GA_LD 72
#define GB_LD 136
#define GS_LD 132
#define A_STG (128 * GA_LD)          // elems per A stage
#define B_STG (64 * GB_LD)
#define GEMM_SMEM ((3 * A_STG + 3 * B_STG) * 2)   // 107520 B; St (67568) aliases

__global__ void __launch_bounds__(256, 2)
gemm_uv_kernel(const float* __restrict__ bu, const float* __restrict__ bv) {
    extern __shared__ char smem[];
    __nv_bfloat16* As = (__nv_bfloat16*)smem;                         // 3 x 128x72
    __nv_bfloat16* Bs = (__nv_bfloat16*)(smem + 3 * A_STG * 2);       // 3 x 64x136
    float*         St = (float*)smem;                                  // [128ch][132] alias

    int m0 = blockIdx.x * 128;
    int n0 = blockIdx.y * 128;
    int mode = blockIdx.z;                                             // 0:u 1:v
    const __nv_bfloat16* W = mode ? g_wvb : g_wub;
    const float* bias = mode ? bv : bu;

    int tid = threadIdx.x;
    int wid = tid >> 5;
    int wm = wid & 3, wn = wid >> 2;

    wmma::fragment<wmma::accumulator, 16, 16, 16, float> acc[2][4];
#pragma unroll
    for (int i = 0; i < 2; i++)
#pragma unroll
        for (int j = 0; j < 4; j++) wmma::fill_fragment(acc[i][j], 0.f);

#define UV_LOAD(k0, st)                                                              \
    {                                                                                \
        _Pragma("unroll")                                                            \
        for (int l = 0; l < 4; l++) {            /* A: 128 rows x 8 chunks */        \
            int a = tid + 256 * l;                                                   \
            int row = a >> 3, ch = a & 7;                                            \
            cpa16(As + (st) * A_STG + row * GA_LD + ch * 8,                          \
                  g_xnb + (size_t)(m0 + row) * EDIM + (k0) + ch * 8);                \
        }                                                                            \
        _Pragma("unroll")                                                            \
        for (int l = 0; l < 4; l++) {            /* B: 64 rows x 16 chunks */        \
            int a = tid + 256 * l;                                                   \
            int row = a >> 4, ch = a & 15;                                           \
            cpa16(Bs + (st) * B_STG + row * GB_LD + ch * 8,                          \
                  W + (size_t)((k0) + row) * D1 + n0 + ch * 8);                      \
        }                                                                            \
        CP_COMMIT();                                                                 \
    }

    UV_LOAD(0, 0);
    UV_LOAD(64, 1);
    const int NT = EDIM / 64;                    // 6
    for (int t = 0; t < NT; t++) {
        if (t + 1 < NT) CP_WAIT1(); else CP_WAIT0();
        __syncthreads();                         // single barrier per iter
        if (t + 2 < NT) UV_LOAD((t + 2) * 64, (t + 2) % 3);
        const __nv_bfloat16* Ac = As + (t % 3) * A_STG;
        const __nv_bfloat16* Bc = Bs + (t % 3) * B_STG;
#pragma unroll
        for (int kk = 0; kk < 64; kk += 16) {
            wmma::fragment<wmma::matrix_a, 16, 16, 16, __nv_bfloat16, wmma::row_major> af[2];
            wmma::fragment<wmma::matrix_b, 16, 16, 16, __nv_bfloat16, wmma::row_major> bf[4];
#pragma unroll
            for (int i = 0; i < 2; i++)
                wmma::load_matrix_sync(af[i], Ac + (wm * 32 + 16 * i) * GA_LD + kk, GA_LD);
#pragma unroll
            for (int j = 0; j < 4; j++)
                wmma::load_matrix_sync(bf[j], Bc + kk * GB_LD + wn * 64 + 16 * j, GB_LD);
#pragma unroll
            for (int i = 0; i < 2; i++)
#pragma unroll
                for (int j = 0; j < 4; j++) wmma::mma_sync(acc[i][j], af[i], bf[j], acc[i][j]);
        }
    }
    __syncthreads();                             // all compute done before St alias
    // col-major store: element (tok i, ch j) -> St[j * GS_LD + i]
#pragma unroll
    for (int i = 0; i < 2; i++)
#pragma unroll
        for (int j = 0; j < 4; j++)
            wmma::store_matrix_sync(St + (wm * 32 + 16 * i) + (size_t)(wn * 64 + 16 * j) * GS_LD,
                                    acc[i][j], GS_LD, wmma::mem_col_major);
    __syncthreads();
    // silu + transposed write: [c][tok], bf16, float4 reads / 8B stores
    {
        int lane = tid & 31;
        int wrp  = tid >> 5;
        __nv_bfloat16* dst = mode ? g_vt : g_ut;
#pragma unroll
        for (int l = 0; l < 16; l++) {
            int j = l * 8 + wrp;                 // channel 0..127
            float4 v4 = *(const float4*)(St + (size_t)j * GS_LD + lane * 4);
            float b = bias[n0 + j];
            float s0 = silu_fast(v4.x + b), s1 = silu_fast(v4.y + b);
            float s2 = silu_fast(v4.z + b), s3 = silu_fast(v4.w + b);
            __nv_bfloat162 h0 = __floats2bfloat162_rn(s0, s1);
            __nv_bfloat162 h1 = __floats2bfloat162_rn(s2, s3);
            uint2 pk;
            pk.x = *(unsigned int*)&h0;
            pk.y = *(unsigned int*)&h1;
            *(uint2*)(dst + (size_t)(n0 + j) * TOK + m0 + lane * 4) = pk;
        }
    }
#undef UV_LOAD
}

// ---------------- RPE norm: g_rB = relu(srms(reduce(g_rP) + bias)) -----------
__global__ void rpe_norm(const float* __restrict__ lb1, const float* __restrict__ lb2,
                         int boff) {
    int wid = threadIdx.x >> 5, lane = threadIdx.x & 31;
    int g = blockIdx.x * 8 + wid;                // 0..255
    int net = g >> 7, r = g & 127;
    const float* P  = g_rP + (size_t)net * RP_NET + (size_t)r * 768;
    const float* Bb = (net ? lb2 : lb1) + boff;
    float4 v[4];
#pragma unroll
    for (int i = 0; i < 4; i++) {
        int q = lane + 32 * i;
        float4 p0 = ((const float4*)(P + 0 * RP_SL))[q];
        float4 p1 = ((const float4*)(P + 1 * RP_SL))[q];
        float4 p2 = ((const float4*)(P + 2 * RP_SL))[q];
        float4 p3 = ((const float4*)(P + 3 * RP_SL))[q];
        float4 b4 = ((const float4*)Bb)[q];
        v[i].x = p0.x + p1.x + p2.x + p3.x + b4.x;
        v[i].y = p0.y + p1.y + p2.y + p3.y + b4.y;
        v[i].z = p0.z + p1.z + p2.z + p3.z + b4.z;
        v[i].w = p0.w + p1.w + p2.w + p3.w + b4.w;
    }
    float ss = 0.f;
#pragma unroll
    for (int i = 0; i < 4; i++)
        ss += v[i].x * v[i].x + v[i].y * v[i].y + v[i].z * v[i].z + v[i].w * v[i].w;
#pragma unroll
    for (int o = 16; o; o >>= 1) ss += __shfl_xor_sync(0xffffffffu, ss, o);
    float rs = rsqrtf(ss / (float)RPEW + 1e-6f);
    float* Xo = g_rB + (size_t)net * 128 * RPEW + (size_t)r * RPEW;
#pragma unroll
    for (int i = 0; i < 4; i++) {
        float4 o4;
        o4.x = fmaxf(v[i].x * rs, 0.f); o4.y = fmaxf(v[i].y * rs, 0.f);
        o4.z = fmaxf(v[i].z * rs, 0.f); o4.w = fmaxf(v[i].w * rs, 0.f);
        ((float4*)Xo)[lane + 32 * i] = o4;
    }
}

// ---------------- RPE GEMM (TF32, split-K): partial = g_rB[:,ks*128:+128]@W --
#define RX_LD 36
#define RX_STG (128 * RX_LD)         // 4608 floats / stage
#define RW_LD 68
#define RW_STG (32 * RW_LD)          // 2176 floats / stage
#define RG_SMEM (2 * RX_STG * 4 + 2 * RW_STG * 4)   // 54272 B; St [128][68] aliases

__global__ void rpe_gemm(const float* __restrict__ wA, const float* __restrict__ wB,
                         int woff, int N) {
    extern __shared__ char sm[];
    float* Xs = (float*)sm;                         // 2 x [128][36]
    float* Ws = (float*)(sm + 2 * RX_STG * 4);      // 2 x [32][68]
    float* St = (float*)sm;                         // [128][68] alias

    int net = blockIdx.z;
    int ks  = blockIdx.y;                           // k-slice 0..3
    int c0  = blockIdx.x * 64;
    const float* W  = (net ? wB : wA) + woff;
    const float* Xi = g_rB + (size_t)net * 128 * RPEW;
    int kbase = ks * 128;

    int tid = threadIdx.x;
    int wid = tid >> 5;
    int wm = wid & 3, wn = wid >> 2;                // warp tile 32 rows x 32 cols

    wmma::fragment<wmma::accumulator, 16, 16, 8, float> acc[2][2];
#pragma unroll
    for (int i = 0; i < 2; i++)
#pragma unroll
        for (int j = 0; j < 2; j++) wmma::fill_fragment(acc[i][j], 0.f);

#define RG_LOAD(k0, st)                                                              \
    {                                                                                \
        _Pragma("unroll")                                                            \
        for (int l = 0; l < 4; l++) {            /* X: 128 rows x 8 chunks(4f) */    \
            int a = tid + 256 * l;                                                   \
            int row = a >> 3, ch = a & 7;                                            \
            cpa16(Xs + (st) * RX_STG + row * RX_LD + ch * 4,                         \
                  Xi + (size_t)row * RPEW + kbase + (k0) + ch * 4);                  \
        }                                                                            \
        _Pragma("unroll")                                                            \
        for (int l = 0; l < 2; l++) {            /* W: 32 rows x 16 chunks(4f) */    \
            int a = tid + 256 * l;                                                   \
            int row = a >> 4, ch = a & 15;                                           \
            cpa16(Ws + (st) * RW_STG + row * RW_LD + ch * 4,                         \
                  W + (size_t)(kbase + (k0) + row) * N + c0 + ch * 4);               \
        }                                                                            \
        CP_COMMIT();                                                                 \
    }

    RG_LOAD(0, 0);
    const int NT = 4;                            // 128 / 32
    for (int t = 0; t < NT; t++) {
        if (t + 1 < NT) { RG_LOAD((t + 1) * 32, (t + 1) & 1); CP_WAIT1(); }
        else           { CP_WAIT0(); }
        __syncthreads();
        const float* Xc = Xs + (t & 1) * RX_STG;
        const float* Wc = Ws + (t & 1) * RW_STG;
#pragma unroll
        for (int kk = 0; kk < 32; kk += 8) {
            wmma::fragment<wmma::matrix_a, 16, 16, 8, wmma::precision::tf32, wmma::row_major> af[2];
            wmma::fragment<wmma::matrix_b, 16, 16, 8, wmma::precision::tf32, wmma::row_major> bf[2];
#pragma unroll
            for (int i = 0; i < 2; i++) {
                wmma::load_matrix_sync(af[i], Xc + (wm * 32 + 16 * i) * RX_LD + kk, RX_LD);
#pragma unroll
                for (int e = 0; e < af[i].num_elements; e++)
                    af[i].x[e] = wmma::__float_to_tf32(af[i].x[e]);
            }
#pragma unroll
            for (int j = 0; j < 2; j++) {
                wmma::load_matrix_sync(bf[j], Wc + kk * RW_LD + wn * 32 + 16 * j, RW_LD);
#pragma unroll
                for (int e = 0; e < bf[j].num_elements; e++)
                    bf[j].x[e] = wmma::__float_to_tf32(bf[j].x[e]);
            }
#pragma unroll
            for (int i = 0; i < 2; i++)
#pragma unroll
                for (int j = 0; j < 2; j++) wmma::mma_sync(acc[i][j], af[i], bf[j], acc[i][j]);
        }
        __syncthreads();
    }
#pragma unroll
    for (int i = 0; i < 2; i++)
#pragma unroll
        for (int j = 0; j < 2; j++)
            wmma::store_matrix_sync(St + (wm * 32 + 16 * i) * RW_LD + wn * 32 + 16 * j,
                                    acc[i][j], RW_LD, wmma::mem_row_major);
    __syncthreads();
    float* Po = g_rP + (size_t)net * RP_NET + (size_t)ks * RP_SL;
#pragma unroll
    for (int l = 0; l < 32; l++) {
        int a = tid + 256 * l;                   // 8192 elems
        int r = a >> 6, c = a & 63;
        Po[(size_t)r * 768 + c0 + c] = St[r * RW_LD + c];
    }
#undef RG_LOAD
}

// ---------------- Toeplitz tables: reduce final partials + bias + build ------
__global__ void toep_kernel(const float* __restrict__ ob1, const float* __restrict__ ob2) {
    __shared__ float a1[128], a2[128];
    int c = blockIdx.x;
    int tid = threadIdx.x;
    if (tid < 128) {
        const float* P1 = g_rP + (size_t)tid * 768 + c;            // net 0 (r1, W-axis)
        const float* P2 = g_rP + RP_NET + (size_t)tid * 768 + c;   // net 1 (r2, H-axis)
        a1[tid] = P1[0] + P1[RP_SL] + P1[2 * RP_SL] + P1[3 * RP_SL] + ob1[c];
        a2[tid] = P2[0] + P2[RP_SL] + P2[2 * RP_SL] + P2[3 * RP_SL] + ob2[c];
        g_at1[(size_t)c * 128 + tid] = a1[tid];
        g_at2[(size_t)c * 128 + tid] = a2[tid];
    }
    __syncthreads();
#pragma unroll
    for (int l = 0; l < 16; l++) {
        int idx = tid + 256 * l;                 // 0..4095
        int r = idx >> 6, s = idx & 63;
        g_T2b [(size_t)c * 4096 + idx] = __float2bfloat16(a2[(r - s) & 127]);  // T2[i][k]
        g_T1tb[(size_t)c * 4096 + idx] = __float2bfloat16(a1[(s - r) & 127]);  // T1t[k][j]
    }
}

// ---------------- TNO conv: 2 channels x 2 batches per block ------------------
// T tiles + fragments reused across both batches; acc for both in regs.
#define CT_LD 72
#define CT_CH 4608            // 64*72 elems per channel tile
#define CONV_SMEM 73728       // T2(18432)+T1t(18432)+V0(18432)+V1(18432); St(36864) aliases V

__global__ void __launch_bounds__(256, 2)
conv_kernel() {
    extern __shared__ char sm[];
    __nv_bfloat16* T2s = (__nv_bfloat16*)(sm);
    __nv_bfloat16* T1s = (__nv_bfloat16*)(sm + 18432);
    __nv_bfloat16* V0  = (__nv_bfloat16*)(sm + 36864);
    __nv_bfloat16* V1  = (__nv_bfloat16*)(sm + 55296);
    float*         St  = (float*)(sm + 36864);         // one batch [2ch][64][72] f32

    int c0 = blockIdx.x * 2;
    int b0 = blockIdx.y * 2;
    int tid = threadIdx.x;

#pragma unroll
    for (int l = 0; l < 4; l++) {                       // 1024 uint4 each tensor
        int a = tid + 256 * l;
        int cc = a >> 9, rq = a & 511;
        int r = rq >> 3, q = rq & 7;
        cpa16(T2s + cc * CT_CH + r * CT_LD + q * 8,
              g_T2b + (size_t)(c0 + cc) * 4096 + r * 64 + q * 8);
        cpa16(T1s + cc * CT_CH + r * CT_LD + q * 8,
              g_T1tb + (size_t)(c0 + cc) * 4096 + r * 64 + q * 8);
        cpa16(V0 + cc * CT_CH + r * CT_LD + q * 8,
              g_vt + (size_t)(c0 + cc) * TOK + b0 * 4096 + r * 64 + q * 8);
        cpa16(V1 + cc * CT_CH + r * CT_LD + q * 8,
              g_vt + (size_t)(c0 + cc) * TOK + (b0 + 1) * 4096 + r * 64 + q * 8);
    }
    CP_COMMIT();
    CP_WAIT0();
    __syncthreads();

    int wid = tid >> 5;
    int cc  = wid >> 2;                                 // 2 channels, 4 warps each
    int r0  = (wid & 3) * 16;                           // 16 rows per warp
    __nv_bfloat16* V0c = V0  + cc * CT_CH;
    __nv_bfloat16* V1c = V1  + cc * CT_CH;
    __nv_bfloat16* T2c = T2s + cc * CT_CH;
    __nv_bfloat16* T1c = T1s + cc * CT_CH;

    wmma::fragment<wmma::accumulator, 16, 16, 16, float> acc0[4], acc1[4];
#pragma unroll
    for (int j = 0; j < 4; j++) { wmma::fill_fragment(acc0[j], 0.f);
                                  wmma::fill_fragment(acc1[j], 0.f); }

#pragma unroll
    for (int kt = 0; kt < 4; kt++) {
        wmma::fragment<wmma::matrix_a, 16, 16, 16, __nv_bfloat16, wmma::row_major> af;
        wmma::fragment<wmma::matrix_b, 16, 16, 16, __nv_bfloat16, wmma::row_major> bf[4];
        // product 1: T2 @ V  (af reused for BOTH batches)
        wmma::load_matrix_sync(af, T2c + r0 * CT_LD + kt * 16, CT_LD);
#pragma unroll
        for (int j = 0; j < 4; j++)
            wmma::load_matrix_sync(bf[j], V0c + kt * 16 * CT_LD + 16 * j, CT_LD);
#pragma unroll
        for (int j = 0; j < 4; j++) wmma::mma_sync(acc0[j], af, bf[j], acc0[j]);
#pragma unroll
        for (int j = 0; j < 4; j++)
            wmma::load_matrix_sync(bf[j], V1c + kt * 16 * CT_LD + 16 * j, CT_LD);
#pragma unroll
        for (int j = 0; j < 4; j++) wmma::mma_sync(acc1[j], af, bf[j], acc1[j]);
        // product 2: V @ T1t  (bf = T1t reused for BOTH batches)
#pragma unroll
        for (int j = 0; j < 4; j++)
            wmma::load_matrix_sync(bf[j], T1c + kt * 16 * CT_LD + 16 * j, CT_LD);
        wmma::load_matrix_sync(af, V0c + r0 * CT_LD + kt * 16, CT_LD);
#pragma unroll
        for (int j = 0; j < 4; j++) wmma::mma_sync(acc0[j], af, bf[j], acc0[j]);
        wmma::load_matrix_sync(af, V1c + r0 * CT_LD + kt * 16, CT_LD);
#pragma unroll
        for (int j = 0; j < 4; j++) wmma::mma_sync(acc1[j], af, bf[j], acc1[j]);
    }
    // two-round epilogue: St aliases V (dead after mma)
#pragma unroll
    for (int bb = 0; bb < 2; bb++) {
        __syncthreads();
#pragma unroll
        for (int j = 0; j < 4; j++)
            wmma::store_matrix_sync(St + cc * CT_CH + r0 * CT_LD + 16 * j,
                                    bb ? acc1[j] : acc0[j], CT_LD, wmma::mem_row_major);
        __syncthreads();
        int b = b0 + bb;
#pragma unroll 4
        for (int l = 0; l < 32; l++) {                  // g = u * tno -> bf16
            int a = tid + 256 * l;                      // 0..8191
            int cc2 = a >> 12, hw = a & 4095;
            int h = hw >> 6, w = hw & 63;
            float t = St[cc2 * CT_CH + h * CT_LD + w];
            float u = __bfloat162float(g_ut[(size_t)(c0 + cc2) * TOK + b * 4096 + hw]);
            g_gt[(size_t)(c0 + cc2) * TOK + b * 4096 + hw] = __float2bfloat16(t * u);
        }
    }
}

// ---------------- final GEMM: out = g @ Wo + bo + x, 3-stage 1-sync ----------
#define GSO_LD 132
#define GO_LD 136
#define O_STG (64 * GO_LD)
#define GOUT_SMEM (6 * O_STG * 2)     // 104448 B; St (128x132 f32 = 67584) aliases

__global__ void __launch_bounds__(256, 2)
gemm_out_kernel(const float* __restrict__ x, const float* __restrict__ bo,
                float* __restrict__ out) {
    extern __shared__ char smem[];
    __nv_bfloat16* As = (__nv_bfloat16*)smem;                     // 3 x [64][136]
    __nv_bfloat16* Bs = (__nv_bfloat16*)(smem + 3 * O_STG * 2);   // 3 x [64][136]
    float*         St = (float*)smem;                              // 128x132 alias

    int m0 = blockIdx.x * 128;
    int n0 = blockIdx.y * 128;
    int tid = threadIdx.x;
    int wid = tid >> 5;
    int wm = wid & 3, wn = wid >> 2;

    wmma::fragment<wmma::accumulator, 16, 16, 16, float> acc[2][4];
#pragma unroll
    for (int i = 0; i < 2; i++)
#pragma unroll
        for (int j = 0; j < 4; j++) wmma::fill_fragment(acc[i][j], 0.f);

#define GO_LOAD(k0, st)                                                              \
    {                                                                                \
        _Pragma("unroll")                                                            \
        for (int l = 0; l < 4; l++) {            /* A: 64 k-rows x 16 m-chunks */    \
            int a = tid + 256 * l;                                                   \
            int row = a >> 4, ch = a & 15;                                           \
            cpa16(As + (st) * O_STG + row * GO_LD + ch * 8,                          \
                  g_gt + (size_t)((k0) + row) * TOK + m0 + ch * 8);                  \
        }                                                                            \
        _Pragma("unroll")                                                            \
        for (int l = 0; l < 4; l++) {            /* B: 64 k-rows x 16 n-chunks */    \
            int a = tid + 256 * l;                                                   \
            int row = a >> 4, ch = a & 15;                                           \
            cpa16(Bs + (st) * O_STG + row * GO_LD + ch * 8,                          \
                  g_wob + (size_t)((k0) + row) * EDIM + n0 + ch * 8);                \
        }                                                                            \
        CP_COMMIT();                                                                 \
    }

    GO_LOAD(0, 0);
    GO_LOAD(64, 1);
    const int NT = D1 / 64;                      // 12
    for (int t = 0; t < NT; t++) {
        if (t + 1 < NT) CP_WAIT1(); else CP_WAIT0();
        __syncthreads();                         // single barrier per iter
        if (t + 2 < NT) GO_LOAD((t + 2) * 64, (t + 2) % 3);
        const __nv_bfloat16* Ac = As + (t % 3) * O_STG;
        const __nv_bfloat16* Bc = Bs + (t % 3) * O_STG;
#pragma unroll
        for (int kk = 0; kk < 64; kk += 16) {
            wmma::fragment<wmma::matrix_a, 16, 16, 16, __nv_bfloat16, wmma::col_major> af[2];
            wmma::fragment<wmma::matrix_b, 16, 16, 16, __nv_bfloat16, wmma::row_major> bf[4];
#pragma unroll
            for (int i = 0; i < 2; i++)
                wmma::load_matrix_sync(af[i], Ac + kk * GO_LD + wm * 32 + 16 * i, GO_LD);
#pragma unroll
            for (int j = 0; j < 4; j++)
                wmma::load_matrix_sync(bf[j], Bc + kk * GO_LD + wn * 64 + 16 * j, GO_LD);
#pragma unroll
            for (int i = 0; i < 2; i++)
#pragma unroll
                for (int j = 0; j < 4; j++) wmma::mma_sync(acc[i][j], af[i], bf[j], acc[i][j]);
        }
    }
    __syncthreads();                             // all compute done before St alias
#pragma unroll
    for (int i = 0; i < 2; i++)
#pragma unroll
        for (int j = 0; j < 4; j++)
            wmma::store_matrix_sync(St + (wm * 32 + 16 * i) * GSO_LD + wn * 64 + 16 * j,
                                    acc[i][j], GSO_LD, wmma::mem_row_major);
    __syncthreads();
#pragma unroll 4
    for (int l = 0; l < 64; l++) {
        int a = tid + 256 * l;
        int i = a >> 7, j = a & 127;             // j contiguous -> coalesced out/x
        size_t go = (size_t)(m0 + i) * EDIM + n0 + j;
        out[go] = St[i * GSO_LD + j] + bo[n0 + j] + x[go];
    }
#undef GO_LOAD
}

// ---------------- launch ------------------------------------------------------
extern "C" void kernel_launch(void* const* d_in, const int* in_sizes, int n_in,
                              void* d_out, int out_size) {
    (void)in_sizes; (void)n_in; (void)out_size;
    const float* x     = (const float*)d_in[0];
    const float* Wu    = (const float*)d_in[3];
    const float* bu    = (const float*)d_in[4];
    const float* Wv    = (const float*)d_in[5];
    const float* bv    = (const float*)d_in[6];
    const float* Wo    = (const float*)d_in[7];
    const float* bo    = (const float*)d_in[8];
    const float* r1_pw = (const float*)d_in[9];
    const float* r1_pb = (const float*)d_in[10];
    const float* r1_lw = (const float*)d_in[11];
    const float* r1_lb = (const float*)d_in[12];
    const float* r1_ow = (const float*)d_in[13];
    const float* r1_ob = (const float*)d_in[14];
    const float* r2_pw = (const float*)d_in[15];
    const float* r2_pb = (const float*)d_in[16];
    const float* r2_lw = (const float*)d_in[17];
    const float* r2_lb = (const float*)d_in[18];
    const float* r2_ow = (const float*)d_in[19];
    const float* r2_ob = (const float*)d_in[20];
    float* out = (float*)d_out;

    cudaFuncSetAttribute(gemm_uv_kernel,  cudaFuncAttributeMaxDynamicSharedMemorySize, GEMM_SMEM);
    cudaFuncSetAttribute(gemm_out_kernel, cudaFuncAttributeMaxDynamicSharedMemorySize, GOUT_SMEM);
    cudaFuncSetAttribute(conv_kernel,     cudaFuncAttributeMaxDynamicSharedMemorySize, CONV_SMEM);
    cudaFuncSetAttribute(rpe_gemm,        cudaFuncAttributeMaxDynamicSharedMemorySize, RG_SMEM);

    mega_prep<<<5280, 256>>>(x, Wu, Wv, Wo, r1_pw, r1_pb, r2_pw, r2_pb);         // 0
    rpe_gemm<<<dim3(8, 4, 2), 256, RG_SMEM>>>(r1_lw, r2_lw, 0, RPEW);            // 1: layer0
    rpe_norm<<<32, 256>>>(r1_lb, r2_lb, 0);                                      // 2
    gemm_uv_kernel<<<dim3(TOK / 128, D1 / 128, 2), 256, GEMM_SMEM>>>(bu, bv);    // 3 (profiled)
    rpe_gemm<<<dim3(8, 4, 2), 256, RG_SMEM>>>(r1_lw, r2_lw, RPEW * RPEW, RPEW);  // 4: layer1
    rpe_norm<<<32, 256>>>(r1_lb, r2_lb, RPEW);                                   // 5
    rpe_gemm<<<dim3(8, 4, 2), 256, RG_SMEM>>>(r1_lw, r2_lw, 2 * RPEW * RPEW, RPEW); // 6: layer2
    rpe_norm<<<32, 256>>>(r1_lb, r2_lb, 2 * RPEW);                               // 7
    rpe_gemm<<<dim3(12, 4, 2), 256, RG_SMEM>>>(r1_ow, r2_ow, 0, D1);             // 8: final
    toep_kernel<<<D1, 256>>>(r1_ob, r2_ob);                                      // 9

    conv_kernel<<<dim3(D1 / 2, BSZ / 2), 256, CONV_SMEM>>>();                    // 10
    gemm_out_kernel<<<dim3(TOK / 128, EDIM / 128), 256, GOUT_SMEM>>>(x, bo, out);// 11
}

// round 14
// speedup vs baseline: 1.2156x; 1.2156x over previous
#include <cuda_runtime.h>
#include <cuda_bf16.h>
#include <mma.h>
#include <math.h>
#include <stdint.h>

using namespace nvcuda;

// ---------------- problem constants ----------------
#define TOK   32768            // B*H*W
#define EDIM  384
#define D1    768
#define BSZ   8
#define NSP   64               // H = W = 64
#define RPEW  512
#define RP_SL 98304            // 128*768 floats per k-slice
#define RP_NET (4 * RP_SL)     // per-net partial block

// ---------------- device scratch (allocation-free) ----------------
__device__ __align__(256) __nv_bfloat16 g_xnb[(size_t)TOK * EDIM];   // normed x, bf16
__device__ __align__(256) __nv_bfloat16 g_ut [(size_t)D1 * TOK];     // u transposed [c][tok]
__device__ __align__(256) __nv_bfloat16 g_vt [(size_t)D1 * TOK];     // v transposed [c][tok]
__device__ __align__(256) __nv_bfloat16 g_gt [(size_t)D1 * TOK];     // g = u*tno, [c][tok]
__device__ __align__(256) __nv_bfloat16 g_wub[EDIM * D1];            // Wu [k][n]
__device__ __align__(256) __nv_bfloat16 g_wvb[EDIM * D1];            // Wv [k][n]
__device__ __align__(256) __nv_bfloat16 g_wob[D1 * EDIM];            // Wo [k][n]
__device__ __align__(256) float         g_at1[D1 * 128];             // W-axis coeffs [c][lag]
__device__ __align__(256) float         g_at2[D1 * 128];             // H-axis coeffs [c][lag]
__device__ __align__(256) float         g_rP [2 * 4 * 128 * 768];    // split-K partials
__device__ __align__(256) float         g_rB [2 * 128 * RPEW];       // rpe normalized
__device__ __align__(256) __nv_bfloat16 g_T2b [(size_t)D1 * 64 * 64]; // T2[c][i][k]
__device__ __align__(256) __nv_bfloat16 g_T1tb[(size_t)D1 * 64 * 64]; // T1t[c][k][j]

// ---------------- cp.async helpers ----------------
__device__ __forceinline__ void cpa16(void* dst, const void* src) {
    unsigned int s = (unsigned int)__cvta_generic_to_shared(dst);
    asm volatile("cp.async.cg.shared.global [%0], [%1], 16;\n" :: "r"(s), "l"(src));
}
#define CP_COMMIT()  asm volatile("cp.async.commit_group;\n" ::: "memory")
#define CP_WAIT0()   asm volatile("cp.async.wait_group 0;\n" ::: "memory")
#define CP_WAIT1()   asm volatile("cp.async.wait_group 1;\n" ::: "memory")

__device__ __forceinline__ float silu_fast(float v) {
    float th;
    asm("tanh.approx.f32 %0, %1;" : "=f"(th) : "f"(v * 0.5f));
    return 0.5f * v + 0.5f * v * th;             // v * sigmoid(v)
}

// ---------------- fp32 -> bf16 weight convert ----------------
__global__ void cvt_kernel(const float* __restrict__ wu, const float* __restrict__ wv,
                           const float* __restrict__ wo) {
    int i = blockIdx.x * 256 + threadIdx.x;      // 294912 elems each
    if (i < EDIM * D1) {
        g_wub[i] = __float2bfloat16(wu[i]);
        g_wvb[i] = __float2bfloat16(wv[i]);
        g_wob[i] = __float2bfloat16(wo[i]);
    }
}

// ---------------- SimpleRMSNorm (one warp / token) ----------------
__global__ void norm_kernel(const float* __restrict__ x) {
    int w    = (blockIdx.x * blockDim.x + threadIdx.x) >> 5;
    int lane = threadIdx.x & 31;
    if (w >= TOK) return;
    const float* xr = x + (size_t)w * EDIM;
    float v[12], s = 0.f;
#pragma unroll
    for (int i = 0; i < 12; i++) { v[i] = xr[lane + 32 * i]; s += v[i] * v[i]; }
#pragma unroll
    for (int o = 16; o; o >>= 1) s += __shfl_xor_sync(0xffffffffu, s, o);
    float r = rsqrtf(s / (float)EDIM + 1e-6f);
    __nv_bfloat16* o = g_xnb + (size_t)w * EDIM;
#pragma unroll
    for (int i = 0; i < 12; i++) o[lane + 32 * i] = __float2bfloat16(v[i] * r);
}

// ---------------- GEMM: u/v = silu(xn @ W + b), 128x128 tile -----------------
// 4 warps, each 64x64 warp tile (acc[4][4]); 3-stage 1-sync cp.async pipeline.
#define GA_LD 72
#define GB_LD 136
#define GS_LD 132
#define A_STG (128 * GA_LD)          // elems per A stage
#define B_STG (64 * GB_LD)
#define GEMM_SMEM ((3 * A_STG + 3 * B_STG) * 2)   // 107520 B; St (67568) aliases

__global__ void __launch_bounds__(128, 2)
gemm_uv_kernel(const float* __restrict__ bu, const float* __restrict__ bv) {
    extern __shared__ char smem[];
    __nv_bfloat16* As = (__nv_bfloat16*)smem;                         // 3 x 128x72
    __nv_bfloat16* Bs = (__nv_bfloat16*)(smem + 3 * A_STG * 2);       // 3 x 64x136
    float*         St = (float*)smem;                                  // [128ch][132] alias

    int m0 = blockIdx.x * 128;
    int n0 = blockIdx.y * 128;
    int mode = blockIdx.z;                                             // 0:u 1:v
    const __nv_bfloat16* W = mode ? g_wvb : g_wub;
    const float* bias = mode ? bv : bu;

    int tid = threadIdx.x;                       // 0..127
    int wid = tid >> 5;                          // 0..3
    int wm = wid & 1, wn = wid >> 1;             // 2x2 warp grid, 64x64 each

    wmma::fragment<wmma::accumulator, 16, 16, 16, float> acc[4][4];
#pragma unroll
    for (int i = 0; i < 4; i++)
#pragma unroll
        for (int j = 0; j < 4; j++) wmma::fill_fragment(acc[i][j], 0.f);

#define UV_LOAD(k0, st)                                                              \
    {                                                                                \
        _Pragma("unroll")                                                            \
        for (int l = 0; l < 8; l++) {            /* A: 128 rows x 8 chunks */        \
            int a = tid + 128 * l;                                                   \
            int row = a >> 3, ch = a & 7;                                            \
            cpa16(As + (st) * A_STG + row * GA_LD + ch * 8,                          \
                  g_xnb + (size_t)(m0 + row) * EDIM + (k0) + ch * 8);                \
        }                                                                            \
        _Pragma("unroll")                                                            \
        for (int l = 0; l < 8; l++) {            /* B: 64 rows x 16 chunks */        \
            int a = tid + 128 * l;                                                   \
            int row = a >> 4, ch = a & 15;                                           \
            cpa16(Bs + (st) * B_STG + row * GB_LD + ch * 8,                          \
                  W + (size_t)((k0) + row) * D1 + n0 + ch * 8);                      \
        }                                                                            \
        CP_COMMIT();                                                                 \
    }

    UV_LOAD(0, 0);
    UV_LOAD(64, 1);
    const int NT = EDIM / 64;                    // 6
    for (int t = 0; t < NT; t++) {
        if (t + 1 < NT) CP_WAIT1(); else CP_WAIT0();
        __syncthreads();                         // single barrier per iter
        if (t + 2 < NT) UV_LOAD((t + 2) * 64, (t + 2) % 3);
        const __nv_bfloat16* Ac = As + (t % 3) * A_STG;
        const __nv_bfloat16* Bc = Bs + (t % 3) * B_STG;
#pragma unroll
        for (int kk = 0; kk < 64; kk += 16) {
            wmma::fragment<wmma::matrix_a, 16, 16, 16, __nv_bfloat16, wmma::row_major> af[4];
            wmma::fragment<wmma::matrix_b, 16, 16, 16, __nv_bfloat16, wmma::row_major> bf[4];
#pragma unroll
            for (int i = 0; i < 4; i++)
                wmma::load_matrix_sync(af[i], Ac + (wm * 64 + 16 * i) * GA_LD + kk, GA_LD);
#pragma unroll
            for (int j = 0; j < 4; j++)
                wmma::load_matrix_sync(bf[j], Bc + kk * GB_LD + wn * 64 + 16 * j, GB_LD);
#pragma unroll
            for (int i = 0; i < 4; i++)
#pragma unroll
                for (int j = 0; j < 4; j++) wmma::mma_sync(acc[i][j], af[i], bf[j], acc[i][j]);
        }
    }
    __syncthreads();                             // all compute done before St alias
    // col-major store: element (tok i, ch j) -> St[j * GS_LD + i]
#pragma unroll
    for (int i = 0; i < 4; i++)
#pragma unroll
        for (int j = 0; j < 4; j++)
            wmma::store_matrix_sync(St + (wm * 64 + 16 * i) + (size_t)(wn * 64 + 16 * j) * GS_LD,
                                    acc[i][j], GS_LD, wmma::mem_col_major);
    __syncthreads();
    // silu + transposed write: [c][tok], bf16, float4 reads / 8B stores
    {
        int lane = tid & 31;
        int wrp  = tid >> 5;
        __nv_bfloat16* dst = mode ? g_vt : g_ut;
#pragma unroll
        for (int l = 0; l < 32; l++) {
            int j = l * 4 + wrp;                 // channel 0..127
            float4 v4 = *(const float4*)(St + (size_t)j * GS_LD + lane * 4);
            float b = bias[n0 + j];
            float s0 = silu_fast(v4.x + b), s1 = silu_fast(v4.y + b);
            float s2 = silu_fast(v4.z + b), s3 = silu_fast(v4.w + b);
            __nv_bfloat162 h0 = __floats2bfloat162_rn(s0, s1);
            __nv_bfloat162 h1 = __floats2bfloat162_rn(s2, s3);
            uint2 pk;
            pk.x = *(unsigned int*)&h0;
            pk.y = *(unsigned int*)&h1;
            *(uint2*)(dst + (size_t)(n0 + j) * TOK + m0 + lane * 4) = pk;
        }
    }
#undef UV_LOAD
}

// ---------------- RPE norm: g_rB = relu(srms(X)); reduce 4 k-slices + bias ----
__global__ void rpe_norm(const float* __restrict__ pw1, const float* __restrict__ pb1,
                         const float* __restrict__ pw2, const float* __restrict__ pb2,
                         const float* __restrict__ lb1, const float* __restrict__ lb2,
                         int boff, int fuse0) {
    int wid = threadIdx.x >> 5, lane = threadIdx.x & 31;
    int g = blockIdx.x * 8 + wid;                // 0..255
    int net = g >> 7, r = g & 127;
    float4 v[4];
    if (fuse0) {
        const float* pw = net ? pw2 : pw1;
        const float* pb = net ? pb2 : pb1;
        float p = (r == 0 || r == 64) ? 0.f : (r < 64 ? (float)r : (float)(r - 128));
#pragma unroll
        for (int i = 0; i < 4; i++) {
            float4 w4 = ((const float4*)pw)[lane + 32 * i];
            float4 b4 = ((const float4*)pb)[lane + 32 * i];
            v[i].x = fmaxf(p * w4.x + b4.x, 0.f);
            v[i].y = fmaxf(p * w4.y + b4.y, 0.f);
            v[i].z = fmaxf(p * w4.z + b4.z, 0.f);
            v[i].w = fmaxf(p * w4.w + b4.w, 0.f);
        }
    } else {
        const float* P  = g_rP + (size_t)net * RP_NET + (size_t)r * 768;
        const float* Bb = (net ? lb2 : lb1) + boff;
#pragma unroll
        for (int i = 0; i < 4; i++) {
            int q = lane + 32 * i;
            float4 p0 = ((const float4*)(P + 0 * RP_SL))[q];
            float4 p1 = ((const float4*)(P + 1 * RP_SL))[q];
            float4 p2 = ((const float4*)(P + 2 * RP_SL))[q];
            float4 p3 = ((const float4*)(P + 3 * RP_SL))[q];
            float4 b4 = ((const float4*)Bb)[q];
            v[i].x = p0.x + p1.x + p2.x + p3.x + b4.x;
            v[i].y = p0.y + p1.y + p2.y + p3.y + b4.y;
            v[i].z = p0.z + p1.z + p2.z + p3.z + b4.z;
            v[i].w = p0.w + p1.w + p2.w + p3.w + b4.w;
        }
    }
    float ss = 0.f;
#pragma unroll
    for (int i = 0; i < 4; i++)
        ss += v[i].x * v[i].x + v[i].y * v[i].y + v[i].z * v[i].z + v[i].w * v[i].w;
#pragma unroll
    for (int o = 16; o; o >>= 1) ss += __shfl_xor_sync(0xffffffffu, ss, o);
    float rs = rsqrtf(ss / (float)RPEW + 1e-6f);
    float* Xo = g_rB + (size_t)net * 128 * RPEW + (size_t)r * RPEW;
#pragma unroll
    for (int i = 0; i < 4; i++) {
        float4 o4;
        o4.x = fmaxf(v[i].x * rs, 0.f); o4.y = fmaxf(v[i].y * rs, 0.f);
        o4.z = fmaxf(v[i].z * rs, 0.f); o4.w = fmaxf(v[i].w * rs, 0.f);
        ((float4*)Xo)[lane + 32 * i] = o4;
    }
}

// ---------------- RPE GEMM (TF32, split-K): partial = g_rB[:,ks*128:+128]@W --
#define RX_LD 36
#define RX_STG (128 * RX_LD)         // 4608 floats / stage
#define RW_LD 68
#define RW_STG (32 * RW_LD)          // 2176 floats / stage
#define RG_SMEM (2 * RX_STG * 4 + 2 * RW_STG * 4)   // 54272 B; St [128][68] aliases

__global__ void rpe_gemm(const float* __restrict__ wA, const float* __restrict__ wB,
                         int woff, int N) {
    extern __shared__ char sm[];
    float* Xs = (float*)sm;                         // 2 x [128][36]
    float* Ws = (float*)(sm + 2 * RX_STG * 4);      // 2 x [32][68]
    float* St = (float*)sm;                         // [128][68] alias

    int net = blockIdx.z;
    int ks  = blockIdx.y;                           // k-slice 0..3
    int c0  = blockIdx.x * 64;
    const float* W  = (net ? wB : wA) + woff;
    const float* Xi = g_rB + (size_t)net * 128 * RPEW;
    int kbase = ks * 128;

    int tid = threadIdx.x;
    int wid = tid >> 5;
    int wm = wid & 3, wn = wid >> 2;                // warp tile 32 rows x 32 cols

    wmma::fragment<wmma::accumulator, 16, 16, 8, float> acc[2][2];
#pragma unroll
    for (int i = 0; i < 2; i++)
#pragma unroll
        for (int j = 0; j < 2; j++) wmma::fill_fragment(acc[i][j], 0.f);

#define RG_LOAD(k0, st)                                                              \
    {                                                                                \
        _Pragma("unroll")                                                            \
        for (int l = 0; l < 4; l++) {            /* X: 128 rows x 8 chunks(4f) */    \
            int a = tid + 256 * l;                                                   \
            int row = a >> 3, ch = a & 7;                                            \
            cpa16(Xs + (st) * RX_STG + row * RX_LD + ch * 4,                         \
                  Xi + (size_t)row * RPEW + kbase + (k0) + ch * 4);                  \
        }                                                                            \
        _Pragma("unroll")                                                            \
        for (int l = 0; l < 2; l++) {            /* W: 32 rows x 16 chunks(4f) */    \
            int a = tid + 256 * l;                                                   \
            int row = a >> 4, ch = a & 15;                                           \
            cpa16(Ws + (st) * RW_STG + row * RW_LD + ch * 4,                         \
                  W + (size_t)(kbase + (k0) + row) * N + c0 + ch * 4);               \
        }                                                                            \
        CP_COMMIT();                                                                 \
    }

    RG_LOAD(0, 0);
    const int NT = 4;                            // 128 / 32
    for (int t = 0; t < NT; t++) {
        if (t + 1 < NT) { RG_LOAD((t + 1) * 32, (t + 1) & 1); CP_WAIT1(); }
        else           { CP_WAIT0(); }
        __syncthreads();
        const float* Xc = Xs + (t & 1) * RX_STG;
        const float* Wc = Ws + (t & 1) * RW_STG;
#pragma unroll
        for (int kk = 0; kk < 32; kk += 8) {
            wmma::fragment<wmma::matrix_a, 16, 16, 8, wmma::precision::tf32, wmma::row_major> af[2];
            wmma::fragment<wmma::matrix_b, 16, 16, 8, wmma::precision::tf32, wmma::row_major> bf[2];
#pragma unroll
            for (int i = 0; i < 2; i++) {
                wmma::load_matrix_sync(af[i], Xc + (wm * 32 + 16 * i) * RX_LD + kk, RX_LD);
#pragma unroll
                for (int e = 0; e < af[i].num_elements; e++)
                    af[i].x[e] = wmma::__float_to_tf32(af[i].x[e]);
            }
#pragma unroll
            for (int j = 0; j < 2; j++) {
                wmma::load_matrix_sync(bf[j], Wc + kk * RW_LD + wn * 32 + 16 * j, RW_LD);
#pragma unroll
                for (int e = 0; e < bf[j].num_elements; e++)
                    bf[j].x[e] = wmma::__float_to_tf32(bf[j].x[e]);
            }
#pragma unroll
            for (int i = 0; i < 2; i++)
#pragma unroll
                for (int j = 0; j < 2; j++) wmma::mma_sync(acc[i][j], af[i], bf[j], acc[i][j]);
        }
        __syncthreads();
    }
#pragma unroll
    for (int i = 0; i < 2; i++)
#pragma unroll
        for (int j = 0; j < 2; j++)
            wmma::store_matrix_sync(St + (wm * 32 + 16 * i) * RW_LD + wn * 32 + 16 * j,
                                    acc[i][j], RW_LD, wmma::mem_row_major);
    __syncthreads();
    float* Po = g_rP + (size_t)net * RP_NET + (size_t)ks * RP_SL;
#pragma unroll
    for (int l = 0; l < 32; l++) {
        int a = tid + 256 * l;                   // 8192 elems
        int r = a >> 6, c = a & 63;
        Po[(size_t)r * 768 + c0 + c] = St[r * RW_LD + c];
    }
#undef RG_LOAD
}

// ---------------- Toeplitz tables: reduce final partials + bias + build ------
__global__ void toep_kernel(const float* __restrict__ ob1, const float* __restrict__ ob2) {
    __shared__ float a1[128], a2[128];
    int c = blockIdx.x;
    int tid = threadIdx.x;
    if (tid < 128) {
        const float* P1 = g_rP + (size_t)tid * 768 + c;            // net 0 (r1, W-axis)
        const float* P2 = g_rP + RP_NET + (size_t)tid * 768 + c;   // net 1 (r2, H-axis)
        a1[tid] = P1[0] + P1[RP_SL] + P1[2 * RP_SL] + P1[3 * RP_SL] + ob1[c];
        a2[tid] = P2[0] + P2[RP_SL] + P2[2 * RP_SL] + P2[3 * RP_SL] + ob2[c];
        g_at1[(size_t)c * 128 + tid] = a1[tid];
        g_at2[(size_t)c * 128 + tid] = a2[tid];
    }
    __syncthreads();
#pragma unroll
    for (int l = 0; l < 16; l++) {
        int idx = tid + 256 * l;                 // 0..4095
        int r = idx >> 6, s = idx & 63;
        g_T2b [(size_t)c * 4096 + idx] = __float2bfloat16(a2[(r - s) & 127]);  // T2[i][k]
        g_T1tb[(size_t)c * 4096 + idx] = __float2bfloat16(a1[(s - r) & 127]);  // T1t[k][j]
    }
}

// ---------------- TNO conv: 2 channels x 1 batch per block, cp.async loads ----
#define CT_LD 72
#define CT_CH 4608            // 64*72 elems per channel tile
#define CONV_SMEM 55296       // T2(18432) + T1t(18432) + V(18432); St aliases T2+T1t

__global__ void conv_kernel() {
    extern __shared__ char sm[];
    __nv_bfloat16* T2s = (__nv_bfloat16*)(sm);
    __nv_bfloat16* T1s = (__nv_bfloat16*)(sm + 18432);
    __nv_bfloat16* Vs  = (__nv_bfloat16*)(sm + 36864);
    float*         St  = (float*)sm;                    // 2*64*72*4 = 36864 alias

    int c0 = blockIdx.x * 2;
    int b  = blockIdx.y;
    int tid = threadIdx.x;

#pragma unroll
    for (int l = 0; l < 4; l++) {                       // 1024 uint4 each tensor
        int a = tid + 256 * l;
        int cc = a >> 9, rq = a & 511;
        int r = rq >> 3, q = rq & 7;
        cpa16(T2s + cc * CT_CH + r * CT_LD + q * 8,
              g_T2b + (size_t)(c0 + cc) * 4096 + r * 64 + q * 8);
        cpa16(T1s + cc * CT_CH + r * CT_LD + q * 8,
              g_T1tb + (size_t)(c0 + cc) * 4096 + r * 64 + q * 8);
        cpa16(Vs + cc * CT_CH + r * CT_LD + q * 8,
              g_vt + (size_t)(c0 + cc) * TOK + b * 4096 + r * 64 + q * 8);
    }
    CP_COMMIT();
    CP_WAIT0();
    __syncthreads();

    int wid = tid >> 5;
    int cc  = wid >> 2;                                 // 2 channels, 4 warps each
    int r0  = (wid & 3) * 16;                           // 16 rows per warp
    __nv_bfloat16* Vc  = Vs  + cc * CT_CH;
    __nv_bfloat16* T2c = T2s + cc * CT_CH;
    __nv_bfloat16* T1c = T1s + cc * CT_CH;

    wmma::fragment<wmma::accumulator, 16, 16, 16, float> acc[4];
#pragma unroll
    for (int j = 0; j < 4; j++) wmma::fill_fragment(acc[j], 0.f);

#pragma unroll
    for (int kt = 0; kt < 4; kt++) {
        wmma::fragment<wmma::matrix_a, 16, 16, 16, __nv_bfloat16, wmma::row_major> af;
        wmma::fragment<wmma::matrix_b, 16, 16, 16, __nv_bfloat16, wmma::row_major> bf[4];
        // product 1: T2 @ V
        wmma::load_matrix_sync(af, T2c + r0 * CT_LD + kt * 16, CT_LD);
#pragma unroll
        for (int j = 0; j < 4; j++)
            wmma::load_matrix_sync(bf[j], Vc + kt * 16 * CT_LD + 16 * j, CT_LD);
#pragma unroll
        for (int j = 0; j < 4; j++) wmma::mma_sync(acc[j], af, bf[j], acc[j]);
        // product 2: V @ T1t
        wmma::load_matrix_sync(af, Vc + r0 * CT_LD + kt * 16, CT_LD);
#pragma unroll
        for (int j = 0; j < 4; j++)
            wmma::load_matrix_sync(bf[j], T1c + kt * 16 * CT_LD + 16 * j, CT_LD);
#pragma unroll
        for (int j = 0; j < 4; j++) wmma::mma_sync(acc[j], af, bf[j], acc[j]);
    }
    __syncthreads();                                    // before aliasing T with St
#pragma unroll
    for (int j = 0; j < 4; j++)
        wmma::store_matrix_sync(St + cc * CT_CH + r0 * CT_LD + 16 * j,
                                acc[j], CT_LD, wmma::mem_row_major);
    __syncthreads();
#pragma unroll 4
    for (int l = 0; l < 32; l++) {                      // g = u * tno -> bf16
        int a = tid + 256 * l;                          // 0..8191
        int cc2 = a >> 12, hw = a & 4095;
        int h = hw >> 6, w = hw & 63;
        float t = St[cc2 * CT_CH + h * CT_LD + w];
        float u = __bfloat162float(g_ut[(size_t)(c0 + cc2) * TOK + b * 4096 + hw]);
        g_gt[(size_t)(c0 + cc2) * TOK + b * 4096 + hw] = __float2bfloat16(t * u);
    }
}

// ---------------- final GEMM: out = g @ Wo + bo + x, 3-stage 1-sync ----------
#define GSO_LD 132
#define GO_LD 136
#define O_STG (64 * GO_LD)
#define GOUT_SMEM (6 * O_STG * 2)     // 104448 B; St (128x132 f32 = 67584) aliases

__global__ void __launch_bounds__(256, 2)
gemm_out_kernel(const float* __restrict__ x, const float* __restrict__ bo,
                float* __restrict__ out) {
    extern __shared__ char smem[];
    __nv_bfloat16* As = (__nv_bfloat16*)smem;                     // 3 x [64][136]
    __nv_bfloat16* Bs = (__nv_bfloat16*)(smem + 3 * O_STG * 2);   // 3 x [64][136]
    float*         St = (float*)smem;                              // 128x132 alias

    int m0 = blockIdx.x * 128;
    int n0 = blockIdx.y * 128;
    int tid = threadIdx.x;
    int wid = tid >> 5;
    int wm = wid & 3, wn = wid >> 2;

    wmma::fragment<wmma::accumulator, 16, 16, 16, float> acc[2][4];
#pragma unroll
    for (int i = 0; i < 2; i++)
#pragma unroll
        for (int j = 0; j < 4; j++) wmma::fill_fragment(acc[i][j], 0.f);

#define GO_LOAD(k0, st)                                                              \
    {                                                                                \
        _Pragma("unroll")                                                            \
        for (int l = 0; l < 4; l++) {            /* A: 64 k-rows x 16 m-chunks */    \
            int a = tid + 256 * l;                                                   \
            int row = a >> 4, ch = a & 15;                                           \
            cpa16(As + (st) * O_STG + row * GO_LD + ch * 8,                          \
                  g_gt + (size_t)((k0) + row) * TOK + m0 + ch * 8);                  \
        }                                                                            \
        _Pragma("unroll")                                                            \
        for (int l = 0; l < 4; l++) {            /* B: 64 k-rows x 16 n-chunks */    \
            int a = tid + 256 * l;                                                   \
            int row = a >> 4, ch = a & 15;                                           \
            cpa16(Bs + (st) * O_STG + row * GO_LD + ch * 8,                          \
                  g_wob + (size_t)((k0) + row) * EDIM + n0 + ch * 8);                \
        }                                                                            \
        CP_COMMIT();                                                                 \
    }

    GO_LOAD(0, 0);
    GO_LOAD(64, 1);
    const int NT = D1 / 64;                      // 12
    for (int t = 0; t < NT; t++) {
        if (t + 1 < NT) CP_WAIT1(); else CP_WAIT0();
        __syncthreads();                         // single barrier per iter
        if (t + 2 < NT) GO_LOAD((t + 2) * 64, (t + 2) % 3);
        const __nv_bfloat16* Ac = As + (t % 3) * O_STG;
        const __nv_bfloat16* Bc = Bs + (t % 3) * O_STG;
#pragma unroll
        for (int kk = 0; kk < 64; kk += 16) {
            wmma::fragment<wmma::matrix_a, 16, 16, 16, __nv_bfloat16, wmma::col_major> af[2];
            wmma::fragment<wmma::matrix_b, 16, 16, 16, __nv_bfloat16, wmma::row_major> bf[4];
#pragma unroll
            for (int i = 0; i < 2; i++)
                wmma::load_matrix_sync(af[i], Ac + kk * GO_LD + wm * 32 + 16 * i, GO_LD);
#pragma unroll
            for (int j = 0; j < 4; j++)
                wmma::load_matrix_sync(bf[j], Bc + kk * GO_LD + wn * 64 + 16 * j, GO_LD);
#pragma unroll
            for (int i = 0; i < 2; i++)
#pragma unroll
                for (int j = 0; j < 4; j++) wmma::mma_sync(acc[i][j], af[i], bf[j], acc[i][j]);
        }
    }
    __syncthreads();                             // all compute done before St alias
#pragma unroll
    for (int i = 0; i < 2; i++)
#pragma unroll
        for (int j = 0; j < 4; j++)
            wmma::store_matrix_sync(St + (wm * 32 + 16 * i) * GSO_LD + wn * 64 + 16 * j,
                                    acc[i][j], GSO_LD, wmma::mem_row_major);
    __syncthreads();
#pragma unroll 4
    for (int l = 0; l < 64; l++) {
        int a = tid + 256 * l;
        int i = a >> 7, j = a & 127;             // j contiguous -> coalesced out/x
        size_t go = (size_t)(m0 + i) * EDIM + n0 + j;
        out[go] = St[i * GSO_LD + j] + bo[n0 + j] + x[go];
    }
#undef GO_LOAD
}

// ---------------- launch ------------------------------------------------------
extern "C" void kernel_launch(void* const* d_in, const int* in_sizes, int n_in,
                              void* d_out, int out_size) {
    (void)in_sizes; (void)n_in; (void)out_size;
    const float* x     = (const float*)d_in[0];
    const float* Wu    = (const float*)d_in[3];
    const float* bu    = (const float*)d_in[4];
    const float* Wv    = (const float*)d_in[5];
    const float* bv    = (const float*)d_in[6];
    const float* Wo    = (const float*)d_in[7];
    const float* bo    = (const float*)d_in[8];
    const float* r1_pw = (const float*)d_in[9];
    const float* r1_pb = (const float*)d_in[10];
    const float* r1_lw = (const float*)d_in[11];
    const float* r1_lb = (const float*)d_in[12];
    const float* r1_ow = (const float*)d_in[13];
    const float* r1_ob = (const float*)d_in[14];
    const float* r2_pw = (const float*)d_in[15];
    const float* r2_pb = (const float*)d_in[16];
    const float* r2_lw = (const float*)d_in[17];
    const float* r2_lb = (const float*)d_in[18];
    const float* r2_ow = (const float*)d_in[19];
    const float* r2_ob = (const float*)d_in[20];
    float* out = (float*)d_out;

    cudaFuncSetAttribute(gemm_uv_kernel,  cudaFuncAttributeMaxDynamicSharedMemorySize, GEMM_SMEM);
    cudaFuncSetAttribute(gemm_out_kernel, cudaFuncAttributeMaxDynamicSharedMemorySize, GOUT_SMEM);
    cudaFuncSetAttribute(conv_kernel,     cudaFuncAttributeMaxDynamicSharedMemorySize, CONV_SMEM);
    cudaFuncSetAttribute(rpe_gemm,        cudaFuncAttributeMaxDynamicSharedMemorySize, RG_SMEM);

    cvt_kernel <<<1152, 256>>>(Wu, Wv, Wo);                                      // 0
    norm_kernel<<<4096, 256>>>(x);                                               // 1
    rpe_norm<<<32, 256>>>(r1_pw, r1_pb, r2_pw, r2_pb, r1_lb, r2_lb, 0, 1);       // 2: X0 -> rB
    gemm_uv_kernel<<<dim3(TOK / 128, D1 / 128, 2), 128, GEMM_SMEM>>>(bu, bv);    // 3 (profiled)
    rpe_gemm<<<dim3(8, 4, 2), 256, RG_SMEM>>>(r1_lw, r2_lw, 0, RPEW);            // 4: layer0
    rpe_norm<<<32, 256>>>(r1_pw, r1_pb, r2_pw, r2_pb, r1_lb, r2_lb, 0, 0);       // 5
    rpe_gemm<<<dim3(8, 4, 2), 256, RG_SMEM>>>(r1_lw, r2_lw, RPEW * RPEW, RPEW);  // 6: layer1
    rpe_norm<<<32, 256>>>(r1_pw, r1_pb, r2_pw, r2_pb, r1_lb, r2_lb, RPEW, 0);    // 7
    rpe_gemm<<<dim3(8, 4, 2), 256, RG_SMEM>>>(r1_lw, r2_lw, 2 * RPEW * RPEW, RPEW); // 8: layer2
    rpe_norm<<<32, 256>>>(r1_pw, r1_pb, r2_pw, r2_pb, r1_lb, r2_lb, 2 * RPEW, 0);// 9
    rpe_gemm<<<dim3(12, 4, 2), 256, RG_SMEM>>>(r1_ow, r2_ow, 0, D1);             // 10: final
    toep_kernel<<<D1, 256>>>(r1_ob, r2_ob);                                      // 11: reduce+tables

    conv_kernel<<<dim3(D1 / 2, BSZ), 256, CONV_SMEM>>>();                        // 12
    gemm_out_kernel<<<dim3(TOK / 128, EDIM / 128), 256, GOUT_SMEM>>>(x, bo, out);// 13
}

// round 15
// speedup vs baseline: 1.3127x; 1.0799x over previous
#include <cuda_runtime.h>
#include <cuda_bf16.h>
#include <mma.h>
#include <math.h>
#include <stdint.h>

using namespace nvcuda;

// ---------------- problem constants ----------------
#define TOK   32768            // B*H*W
#define EDIM  384
#define D1    768
#define BSZ   8
#define NSP   64               // H = W = 64
#define RPEW  512
#define RP_SL 98304            // 128*768 floats per k-slice
#define RP_NET (4 * RP_SL)     // per-net partial block

// ---------------- device scratch (allocation-free) ----------------
__device__ __align__(256) __nv_bfloat16 g_xnb[(size_t)TOK * EDIM];   // normed x, bf16
__device__ __align__(256) __nv_bfloat16 g_ut [(size_t)D1 * TOK];     // u transposed [c][tok]
__device__ __align__(256) __nv_bfloat16 g_vt [(size_t)D1 * TOK];     // v transposed [c][tok]
__device__ __align__(256) __nv_bfloat16 g_gt [(size_t)D1 * TOK];     // g = u*tno, [c][tok]
__device__ __align__(256) __nv_bfloat16 g_wub[EDIM * D1];            // Wu [k][n]
__device__ __align__(256) __nv_bfloat16 g_wvb[EDIM * D1];            // Wv [k][n]
__device__ __align__(256) __nv_bfloat16 g_wob[D1 * EDIM];            // Wo [k][n]
__device__ __align__(256) float         g_at1[D1 * 128];             // W-axis coeffs [c][lag]
__device__ __align__(256) float         g_at2[D1 * 128];             // H-axis coeffs [c][lag]
__device__ __align__(256) float         g_rP [2 * 4 * 128 * 768];    // split-K partials
__device__ __align__(256) float         g_rB [2 * 128 * RPEW];       // rpe normalized
__device__ __align__(256) __nv_bfloat16 g_T2b [(size_t)D1 * 64 * 64]; // T2[c][i][k]
__device__ __align__(256) __nv_bfloat16 g_T1tb[(size_t)D1 * 64 * 64]; // T1t[c][k][j]

// ---------------- cp.async helpers ----------------
__device__ __forceinline__ void cpa16(void* dst, const void* src) {
    unsigned int s = (unsigned int)__cvta_generic_to_shared(dst);
    asm volatile("cp.async.cg.shared.global [%0], [%1], 16;\n" :: "r"(s), "l"(src));
}
#define CP_COMMIT()  asm volatile("cp.async.commit_group;\n" ::: "memory")
#define CP_WAIT0()   asm volatile("cp.async.wait_group 0;\n" ::: "memory")
#define CP_WAIT1()   asm volatile("cp.async.wait_group 1;\n" ::: "memory")

__device__ __forceinline__ float silu_fast(float v) {
    float th;
    asm("tanh.approx.f32 %0, %1;" : "=f"(th) : "f"(v * 0.5f));
    return 0.5f * v + 0.5f * v * th;             // v * sigmoid(v)
}

// ---------------- fp32 -> bf16 weight convert ----------------
__global__ void cvt_kernel(const float* __restrict__ wu, const float* __restrict__ wv,
                           const float* __restrict__ wo) {
    int i = blockIdx.x * 256 + threadIdx.x;      // 294912 elems each
    if (i < EDIM * D1) {
        g_wub[i] = __float2bfloat16(wu[i]);
        g_wvb[i] = __float2bfloat16(wv[i]);
        g_wob[i] = __float2bfloat16(wo[i]);
    }
}

// ---------------- SimpleRMSNorm (one warp / token) ----------------
__global__ void norm_kernel(const float* __restrict__ x) {
    int w    = (blockIdx.x * blockDim.x + threadIdx.x) >> 5;
    int lane = threadIdx.x & 31;
    if (w >= TOK) return;
    const float* xr = x + (size_t)w * EDIM;
    float v[12], s = 0.f;
#pragma unroll
    for (int i = 0; i < 12; i++) { v[i] = xr[lane + 32 * i]; s += v[i] * v[i]; }
#pragma unroll
    for (int o = 16; o; o >>= 1) s += __shfl_xor_sync(0xffffffffu, s, o);
    float r = rsqrtf(s / (float)EDIM + 1e-6f);
    __nv_bfloat16* o = g_xnb + (size_t)w * EDIM;
#pragma unroll
    for (int i = 0; i < 12; i++) o[lane + 32 * i] = __float2bfloat16(v[i] * r);
}

// ---------------- GEMM: u/v = silu(xn @ W + b), 128x128 tile -----------------
// 4 warps, each 64x64 warp tile (acc[4][4]); 3-stage 1-sync cp.async pipeline.
#define GA_LD 72
#define GB_LD 136
#define GS_LD 132
#define A_STG (128 * GA_LD)          // elems per A stage
#define B_STG (64 * GB_LD)
#define GEMM_SMEM ((3 * A_STG + 3 * B_STG) * 2)   // 107520 B; St (67568) aliases

__global__ void __launch_bounds__(128, 2)
gemm_uv_kernel(const float* __restrict__ bu, const float* __restrict__ bv) {
    extern __shared__ char smem[];
    __nv_bfloat16* As = (__nv_bfloat16*)smem;                         // 3 x 128x72
    __nv_bfloat16* Bs = (__nv_bfloat16*)(smem + 3 * A_STG * 2);       // 3 x 64x136
    float*         St = (float*)smem;                                  // [128ch][132] alias

    int m0 = blockIdx.x * 128;
    int n0 = blockIdx.y * 128;
    int mode = blockIdx.z;                                             // 0:u 1:v
    const __nv_bfloat16* W = mode ? g_wvb : g_wub;
    const float* bias = mode ? bv : bu;

    int tid = threadIdx.x;                       // 0..127
    int wid = tid >> 5;                          // 0..3
    int wm = wid & 1, wn = wid >> 1;             // 2x2 warp grid, 64x64 each

    wmma::fragment<wmma::accumulator, 16, 16, 16, float> acc[4][4];
#pragma unroll
    for (int i = 0; i < 4; i++)
#pragma unroll
        for (int j = 0; j < 4; j++) wmma::fill_fragment(acc[i][j], 0.f);

#define UV_LOAD(k0, st)                                                              \
    {                                                                                \
        _Pragma("unroll")                                                            \
        for (int l = 0; l < 8; l++) {            /* A: 128 rows x 8 chunks */        \
            int a = tid + 128 * l;                                                   \
            int row = a >> 3, ch = a & 7;                                            \
            cpa16(As + (st) * A_STG + row * GA_LD + ch * 8,                          \
                  g_xnb + (size_t)(m0 + row) * EDIM + (k0) + ch * 8);                \
        }                                                                            \
        _Pragma("unroll")                                                            \
        for (int l = 0; l < 8; l++) {            /* B: 64 rows x 16 chunks */        \
            int a = tid + 128 * l;                                                   \
            int row = a >> 4, ch = a & 15;                                           \
            cpa16(Bs + (st) * B_STG + row * GB_LD + ch * 8,                          \
                  W + (size_t)((k0) + row) * D1 + n0 + ch * 8);                      \
        }                                                                            \
        CP_COMMIT();                                                                 \
    }

    UV_LOAD(0, 0);
    UV_LOAD(64, 1);
    const int NT = EDIM / 64;                    // 6
    for (int t = 0; t < NT; t++) {
        if (t + 1 < NT) CP_WAIT1(); else CP_WAIT0();
        __syncthreads();                         // single barrier per iter
        if (t + 2 < NT) UV_LOAD((t + 2) * 64, (t + 2) % 3);
        const __nv_bfloat16* Ac = As + (t % 3) * A_STG;
        const __nv_bfloat16* Bc = Bs + (t % 3) * B_STG;
#pragma unroll
        for (int kk = 0; kk < 64; kk += 16) {
            wmma::fragment<wmma::matrix_a, 16, 16, 16, __nv_bfloat16, wmma::row_major> af[4];
            wmma::fragment<wmma::matrix_b, 16, 16, 16, __nv_bfloat16, wmma::row_major> bf[4];
#pragma unroll
            for (int i = 0; i < 4; i++)
                wmma::load_matrix_sync(af[i], Ac + (wm * 64 + 16 * i) * GA_LD + kk, GA_LD);
#pragma unroll
            for (int j = 0; j < 4; j++)
                wmma::load_matrix_sync(bf[j], Bc + kk * GB_LD + wn * 64 + 16 * j, GB_LD);
#pragma unroll
            for (int i = 0; i < 4; i++)
#pragma unroll
                for (int j = 0; j < 4; j++) wmma::mma_sync(acc[i][j], af[i], bf[j], acc[i][j]);
        }
    }
    __syncthreads();                             // all compute done before St alias
    // col-major store: element (tok i, ch j) -> St[j * GS_LD + i]
#pragma unroll
    for (int i = 0; i < 4; i++)
#pragma unroll
        for (int j = 0; j < 4; j++)
            wmma::store_matrix_sync(St + (wm * 64 + 16 * i) + (size_t)(wn * 64 + 16 * j) * GS_LD,
                                    acc[i][j], GS_LD, wmma::mem_col_major);
    __syncthreads();
    // silu + transposed write: [c][tok], bf16, float4 reads / 8B stores
    {
        int lane = tid & 31;
        int wrp  = tid >> 5;
        __nv_bfloat16* dst = mode ? g_vt : g_ut;
#pragma unroll
        for (int l = 0; l < 32; l++) {
            int j = l * 4 + wrp;                 // channel 0..127
            float4 v4 = *(const float4*)(St + (size_t)j * GS_LD + lane * 4);
            float b = bias[n0 + j];
            float s0 = silu_fast(v4.x + b), s1 = silu_fast(v4.y + b);
            float s2 = silu_fast(v4.z + b), s3 = silu_fast(v4.w + b);
            __nv_bfloat162 h0 = __floats2bfloat162_rn(s0, s1);
            __nv_bfloat162 h1 = __floats2bfloat162_rn(s2, s3);
            uint2 pk;
            pk.x = *(unsigned int*)&h0;
            pk.y = *(unsigned int*)&h1;
            *(uint2*)(dst + (size_t)(n0 + j) * TOK + m0 + lane * 4) = pk;
        }
    }
#undef UV_LOAD
}

// ---------------- RPE norm: g_rB = relu(srms(X)); reduce 4 k-slices + bias ----
__global__ void rpe_norm(const float* __restrict__ pw1, const float* __restrict__ pb1,
                         const float* __restrict__ pw2, const float* __restrict__ pb2,
                         const float* __restrict__ lb1, const float* __restrict__ lb2,
                         int boff, int fuse0) {
    int wid = threadIdx.x >> 5, lane = threadIdx.x & 31;
    int g = blockIdx.x * 8 + wid;                // 0..255
    int net = g >> 7, r = g & 127;
    float4 v[4];
    if (fuse0) {
        const float* pw = net ? pw2 : pw1;
        const float* pb = net ? pb2 : pb1;
        float p = (r == 0 || r == 64) ? 0.f : (r < 64 ? (float)r : (float)(r - 128));
#pragma unroll
        for (int i = 0; i < 4; i++) {
            float4 w4 = ((const float4*)pw)[lane + 32 * i];
            float4 b4 = ((const float4*)pb)[lane + 32 * i];
            v[i].x = fmaxf(p * w4.x + b4.x, 0.f);
            v[i].y = fmaxf(p * w4.y + b4.y, 0.f);
            v[i].z = fmaxf(p * w4.z + b4.z, 0.f);
            v[i].w = fmaxf(p * w4.w + b4.w, 0.f);
        }
    } else {
        const float* P  = g_rP + (size_t)net * RP_NET + (size_t)r * 768;
        const float* Bb = (net ? lb2 : lb1) + boff;
#pragma unroll
        for (int i = 0; i < 4; i++) {
            int q = lane + 32 * i;
            float4 p0 = ((const float4*)(P + 0 * RP_SL))[q];
            float4 p1 = ((const float4*)(P + 1 * RP_SL))[q];
            float4 p2 = ((const float4*)(P + 2 * RP_SL))[q];
            float4 p3 = ((const float4*)(P + 3 * RP_SL))[q];
            float4 b4 = ((const float4*)Bb)[q];
            v[i].x = p0.x + p1.x + p2.x + p3.x + b4.x;
            v[i].y = p0.y + p1.y + p2.y + p3.y + b4.y;
            v[i].z = p0.z + p1.z + p2.z + p3.z + b4.z;
            v[i].w = p0.w + p1.w + p2.w + p3.w + b4.w;
        }
    }
    float ss = 0.f;
#pragma unroll
    for (int i = 0; i < 4; i++)
        ss += v[i].x * v[i].x + v[i].y * v[i].y + v[i].z * v[i].z + v[i].w * v[i].w;
#pragma unroll
    for (int o = 16; o; o >>= 1) ss += __shfl_xor_sync(0xffffffffu, ss, o);
    float rs = rsqrtf(ss / (float)RPEW + 1e-6f);
    float* Xo = g_rB + (size_t)net * 128 * RPEW + (size_t)r * RPEW;
#pragma unroll
    for (int i = 0; i < 4; i++) {
        float4 o4;
        o4.x = fmaxf(v[i].x * rs, 0.f); o4.y = fmaxf(v[i].y * rs, 0.f);
        o4.z = fmaxf(v[i].z * rs, 0.f); o4.w = fmaxf(v[i].w * rs, 0.f);
        ((float4*)Xo)[lane + 32 * i] = o4;
    }
}

// ---------------- RPE GEMM (TF32, split-K): partial = g_rB[:,ks*128:+128]@W --
#define RX_LD 36
#define RX_STG (128 * RX_LD)         // 4608 floats / stage
#define RW_LD 68
#define RW_STG (32 * RW_LD)          // 2176 floats / stage
#define RG_SMEM (2 * RX_STG * 4 + 2 * RW_STG * 4)   // 54272 B; St [128][68] aliases

__global__ void rpe_gemm(const float* __restrict__ wA, const float* __restrict__ wB,
                         int woff, int N) {
    extern __shared__ char sm[];
    float* Xs = (float*)sm;                         // 2 x [128][36]
    float* Ws = (float*)(sm + 2 * RX_STG * 4);      // 2 x [32][68]
    float* St = (float*)sm;                         // [128][68] alias

    int net = blockIdx.z;
    int ks  = blockIdx.y;                           // k-slice 0..3
    int c0  = blockIdx.x * 64;
    const float* W  = (net ? wB : wA) + woff;
    const float* Xi = g_rB + (size_t)net * 128 * RPEW;
    int kbase = ks * 128;

    int tid = threadIdx.x;
    int wid = tid >> 5;
    int wm = wid & 3, wn = wid >> 2;                // warp tile 32 rows x 32 cols

    wmma::fragment<wmma::accumulator, 16, 16, 8, float> acc[2][2];
#pragma unroll
    for (int i = 0; i < 2; i++)
#pragma unroll
        for (int j = 0; j < 2; j++) wmma::fill_fragment(acc[i][j], 0.f);

#define RG_LOAD(k0, st)                                                              \
    {                                                                                \
        _Pragma("unroll")                                                            \
        for (int l = 0; l < 4; l++) {            /* X: 128 rows x 8 chunks(4f) */    \
            int a = tid + 256 * l;                                                   \
            int row = a >> 3, ch = a & 7;                                            \
            cpa16(Xs + (st) * RX_STG + row * RX_LD + ch * 4,                         \
                  Xi + (size_t)row * RPEW + kbase + (k0) + ch * 4);                  \
        }                                                                            \
        _Pragma("unroll")                                                            \
        for (int l = 0; l < 2; l++) {            /* W: 32 rows x 16 chunks(4f) */    \
            int a = tid + 256 * l;                                                   \
            int row = a >> 4, ch = a & 15;                                           \
            cpa16(Ws + (st) * RW_STG + row * RW_LD + ch * 4,                         \
                  W + (size_t)(kbase + (k0) + row) * N + c0 + ch * 4);               \
        }                                                                            \
        CP_COMMIT();                                                                 \
    }

    RG_LOAD(0, 0);
    const int NT = 4;                            // 128 / 32
    for (int t = 0; t < NT; t++) {
        if (t + 1 < NT) { RG_LOAD((t + 1) * 32, (t + 1) & 1); CP_WAIT1(); }
        else           { CP_WAIT0(); }
        __syncthreads();
        const float* Xc = Xs + (t & 1) * RX_STG;
        const float* Wc = Ws + (t & 1) * RW_STG;
#pragma unroll
        for (int kk = 0; kk < 32; kk += 8) {
            wmma::fragment<wmma::matrix_a, 16, 16, 8, wmma::precision::tf32, wmma::row_major> af[2];
            wmma::fragment<wmma::matrix_b, 16, 16, 8, wmma::precision::tf32, wmma::row_major> bf[2];
#pragma unroll
            for (int i = 0; i < 2; i++) {
                wmma::load_matrix_sync(af[i], Xc + (wm * 32 + 16 * i) * RX_LD + kk, RX_LD);
#pragma unroll
                for (int e = 0; e < af[i].num_elements; e++)
                    af[i].x[e] = wmma::__float_to_tf32(af[i].x[e]);
            }
#pragma unroll
            for (int j = 0; j < 2; j++) {
                wmma::load_matrix_sync(bf[j], Wc + kk * RW_LD + wn * 32 + 16 * j, RW_LD);
#pragma unroll
                for (int e = 0; e < bf[j].num_elements; e++)
                    bf[j].x[e] = wmma::__float_to_tf32(bf[j].x[e]);
            }
#pragma unroll
            for (int i = 0; i < 2; i++)
#pragma unroll
                for (int j = 0; j < 2; j++) wmma::mma_sync(acc[i][j], af[i], bf[j], acc[i][j]);
        }
        __syncthreads();
    }
#pragma unroll
    for (int i = 0; i < 2; i++)
#pragma unroll
        for (int j = 0; j < 2; j++)
            wmma::store_matrix_sync(St + (wm * 32 + 16 * i) * RW_LD + wn * 32 + 16 * j,
                                    acc[i][j], RW_LD, wmma::mem_row_major);
    __syncthreads();
    float* Po = g_rP + (size_t)net * RP_NET + (size_t)ks * RP_SL;
#pragma unroll
    for (int l = 0; l < 32; l++) {
        int a = tid + 256 * l;                   // 8192 elems
        int r = a >> 6, c = a & 63;
        Po[(size_t)r * 768 + c0 + c] = St[r * RW_LD + c];
    }
#undef RG_LOAD
}

// ---------------- Toeplitz tables: reduce final partials + bias + build ------
__global__ void toep_kernel(const float* __restrict__ ob1, const float* __restrict__ ob2) {
    __shared__ float a1[128], a2[128];
    int c = blockIdx.x;
    int tid = threadIdx.x;
    if (tid < 128) {
        const float* P1 = g_rP + (size_t)tid * 768 + c;            // net 0 (r1, W-axis)
        const float* P2 = g_rP + RP_NET + (size_t)tid * 768 + c;   // net 1 (r2, H-axis)
        a1[tid] = P1[0] + P1[RP_SL] + P1[2 * RP_SL] + P1[3 * RP_SL] + ob1[c];
        a2[tid] = P2[0] + P2[RP_SL] + P2[2 * RP_SL] + P2[3 * RP_SL] + ob2[c];
        g_at1[(size_t)c * 128 + tid] = a1[tid];
        g_at2[(size_t)c * 128 + tid] = a2[tid];
    }
    __syncthreads();
#pragma unroll
    for (int l = 0; l < 16; l++) {
        int idx = tid + 256 * l;                 // 0..4095
        int r = idx >> 6, s = idx & 63;
        g_T2b [(size_t)c * 4096 + idx] = __float2bfloat16(a2[(r - s) & 127]);  // T2[i][k]
        g_T1tb[(size_t)c * 4096 + idx] = __float2bfloat16(a1[(s - r) & 127]);  // T1t[k][j]
    }
}

// ---------------- TNO conv: 2 channels x 1 batch per block, cp.async loads ----
#define CT_LD 72
#define CT_CH 4608            // 64*72 elems per channel tile
#define CONV_SMEM 55296       // T2(18432) + T1t(18432) + V(18432); St aliases T2+T1t

__global__ void conv_kernel() {
    extern __shared__ char sm[];
    __nv_bfloat16* T2s = (__nv_bfloat16*)(sm);
    __nv_bfloat16* T1s = (__nv_bfloat16*)(sm + 18432);
    __nv_bfloat16* Vs  = (__nv_bfloat16*)(sm + 36864);
    float*         St  = (float*)sm;                    // 2*64*72*4 = 36864 alias

    int c0 = blockIdx.x * 2;
    int b  = blockIdx.y;
    int tid = threadIdx.x;

#pragma unroll
    for (int l = 0; l < 4; l++) {                       // 1024 uint4 each tensor
        int a = tid + 256 * l;
        int cc = a >> 9, rq = a & 511;
        int r = rq >> 3, q = rq & 7;
        cpa16(T2s + cc * CT_CH + r * CT_LD + q * 8,
              g_T2b + (size_t)(c0 + cc) * 4096 + r * 64 + q * 8);
        cpa16(T1s + cc * CT_CH + r * CT_LD + q * 8,
              g_T1tb + (size_t)(c0 + cc) * 4096 + r * 64 + q * 8);
        cpa16(Vs + cc * CT_CH + r * CT_LD + q * 8,
              g_vt + (size_t)(c0 + cc) * TOK + b * 4096 + r * 64 + q * 8);
    }
    CP_COMMIT();
    CP_WAIT0();
    __syncthreads();

    int wid = tid >> 5;
    int cc  = wid >> 2;                                 // 2 channels, 4 warps each
    int r0  = (wid & 3) * 16;                           // 16 rows per warp
    __nv_bfloat16* Vc  = Vs  + cc * CT_CH;
    __nv_bfloat16* T2c = T2s + cc * CT_CH;
    __nv_bfloat16* T1c = T1s + cc * CT_CH;

    wmma::fragment<wmma::accumulator, 16, 16, 16, float> acc[4];
#pragma unroll
    for (int j = 0; j < 4; j++) wmma::fill_fragment(acc[j], 0.f);

#pragma unroll
    for (int kt = 0; kt < 4; kt++) {
        wmma::fragment<wmma::matrix_a, 16, 16, 16, __nv_bfloat16, wmma::row_major> af;
        wmma::fragment<wmma::matrix_b, 16, 16, 16, __nv_bfloat16, wmma::row_major> bf[4];
        // product 1: T2 @ V
        wmma::load_matrix_sync(af, T2c + r0 * CT_LD + kt * 16, CT_LD);
#pragma unroll
        for (int j = 0; j < 4; j++)
            wmma::load_matrix_sync(bf[j], Vc + kt * 16 * CT_LD + 16 * j, CT_LD);
#pragma unroll
        for (int j = 0; j < 4; j++) wmma::mma_sync(acc[j], af, bf[j], acc[j]);
        // product 2: V @ T1t
        wmma::load_matrix_sync(af, Vc + r0 * CT_LD + kt * 16, CT_LD);
#pragma unroll
        for (int j = 0; j < 4; j++)
            wmma::load_matrix_sync(bf[j], T1c + kt * 16 * CT_LD + 16 * j, CT_LD);
#pragma unroll
        for (int j = 0; j < 4; j++) wmma::mma_sync(acc[j], af, bf[j], acc[j]);
    }
    __syncthreads();                                    // before aliasing T with St
#pragma unroll
    for (int j = 0; j < 4; j++)
        wmma::store_matrix_sync(St + cc * CT_CH + r0 * CT_LD + 16 * j,
                                acc[j], CT_LD, wmma::mem_row_major);
    __syncthreads();
#pragma unroll 4
    for (int l = 0; l < 32; l++) {                      // g = u * tno -> bf16
        int a = tid + 256 * l;                          // 0..8191
        int cc2 = a >> 12, hw = a & 4095;
        int h = hw >> 6, w = hw & 63;
        float t = St[cc2 * CT_CH + h * CT_LD + w];
        float u = __bfloat162float(g_ut[(size_t)(c0 + cc2) * TOK + b * 4096 + hw]);
        g_gt[(size_t)(c0 + cc2) * TOK + b * 4096 + hw] = __float2bfloat16(t * u);
    }
}

// ---------------- final GEMM: out = g @ Wo + bo + x --------------------------
// 4 warps, each 64x64 warp tile (acc[4][4]); 3-stage 1-sync cp.async pipeline.
#define GSO_LD 132
#define GO_LD 136
#define O_STG (64 * GO_LD)
#define GOUT_SMEM (6 * O_STG * 2)     // 104448 B; St (128x132 f32 = 67584) aliases

__global__ void __launch_bounds__(128, 2)
gemm_out_kernel(const float* __restrict__ x, const float* __restrict__ bo,
                float* __restrict__ out) {
    extern __shared__ char smem[];
    __nv_bfloat16* As = (__nv_bfloat16*)smem;                     // 3 x [64][136]
    __nv_bfloat16* Bs = (__nv_bfloat16*)(smem + 3 * O_STG * 2);   // 3 x [64][136]
    float*         St = (float*)smem;                              // 128x132 alias

    int m0 = blockIdx.x * 128;
    int n0 = blockIdx.y * 128;
    int tid = threadIdx.x;                       // 0..127
    int wid = tid >> 5;                          // 0..3
    int wm = wid & 1, wn = wid >> 1;             // 2x2 warp grid, 64x64 each

    wmma::fragment<wmma::accumulator, 16, 16, 16, float> acc[4][4];
#pragma unroll
    for (int i = 0; i < 4; i++)
#pragma unroll
        for (int j = 0; j < 4; j++) wmma::fill_fragment(acc[i][j], 0.f);

#define GO_LOAD(k0, st)                                                              \
    {                                                                                \
        _Pragma("unroll")                                                            \
        for (int l = 0; l < 8; l++) {            /* A: 64 k-rows x 16 m-chunks */    \
            int a = tid + 128 * l;                                                   \
            int row = a >> 4, ch = a & 15;                                           \
            cpa16(As + (st) * O_STG + row * GO_LD + ch * 8,                          \
                  g_gt + (size_t)((k0) + row) * TOK + m0 + ch * 8);                  \
        }                                                                            \
        _Pragma("unroll")                                                            \
        for (int l = 0; l < 8; l++) {            /* B: 64 k-rows x 16 n-chunks */    \
            int a = tid + 128 * l;                                                   \
            int row = a >> 4, ch = a & 15;                                           \
            cpa16(Bs + (st) * O_STG + row * GO_LD + ch * 8,                          \
                  g_wob + (size_t)((k0) + row) * EDIM + n0 + ch * 8);                \
        }                                                                            \
        CP_COMMIT();                                                                 \
    }

    GO_LOAD(0, 0);
    GO_LOAD(64, 1);
    const int NT = D1 / 64;                      // 12
    for (int t = 0; t < NT; t++) {
        if (t + 1 < NT) CP_WAIT1(); else CP_WAIT0();
        __syncthreads();                         // single barrier per iter
        if (t + 2 < NT) GO_LOAD((t + 2) * 64, (t + 2) % 3);
        const __nv_bfloat16* Ac = As + (t % 3) * O_STG;
        const __nv_bfloat16* Bc = Bs + (t % 3) * O_STG;
#pragma unroll
        for (int kk = 0; kk < 64; kk += 16) {
            wmma::fragment<wmma::matrix_a, 16, 16, 16, __nv_bfloat16, wmma::col_major> af[4];
            wmma::fragment<wmma::matrix_b, 16, 16, 16, __nv_bfloat16, wmma::row_major> bf[4];
#pragma unroll
            for (int i = 0; i < 4; i++)
                wmma::load_matrix_sync(af[i], Ac + kk * GO_LD + wm * 64 + 16 * i, GO_LD);
#pragma unroll
            for (int j = 0; j < 4; j++)
                wmma::load_matrix_sync(bf[j], Bc + kk * GO_LD + wn * 64 + 16 * j, GO_LD);
#pragma unroll
            for (int i = 0; i < 4; i++)
#pragma unroll
                for (int j = 0; j < 4; j++) wmma::mma_sync(acc[i][j], af[i], bf[j], acc[i][j]);
        }
    }
    __syncthreads();                             // all compute done before St alias
#pragma unroll
    for (int i = 0; i < 4; i++)
#pragma unroll
        for (int j = 0; j < 4; j++)
            wmma::store_matrix_sync(St + (wm * 64 + 16 * i) * GSO_LD + wn * 64 + 16 * j,
                                    acc[i][j], GSO_LD, wmma::mem_row_major);
    __syncthreads();
    // float4 epilogue: 128 rows x 32 float4 cols
#pragma unroll
    for (int l = 0; l < 32; l++) {
        int a = tid + 128 * l;                   // 0..4095
        int i = a >> 5, jq = a & 31;             // row, float4-col
        float4 s4 = *(const float4*)(St + (size_t)i * GSO_LD + jq * 4);
        float4 b4 = *(const float4*)(bo + n0 + jq * 4);
        size_t go = (size_t)(m0 + i) * EDIM + n0 + jq * 4;
        float4 x4 = *(const float4*)(x + go);
        float4 o4;
        o4.x = s4.x + b4.x + x4.x;
        o4.y = s4.y + b4.y + x4.y;
        o4.z = s4.z + b4.z + x4.z;
        o4.w = s4.w + b4.w + x4.w;
        *(float4*)(out + go) = o4;
    }
#undef GO_LOAD
}

// ---------------- launch ------------------------------------------------------
extern "C" void kernel_launch(void* const* d_in, const int* in_sizes, int n_in,
                              void* d_out, int out_size) {
    (void)in_sizes; (void)n_in; (void)out_size;
    const float* x     = (const float*)d_in[0];
    const float* Wu    = (const float*)d_in[3];
    const float* bu    = (const float*)d_in[4];
    const float* Wv    = (const float*)d_in[5];
    const float* bv    = (const float*)d_in[6];
    const float* Wo    = (const float*)d_in[7];
    const float* bo    = (const float*)d_in[8];
    const float* r1_pw = (const float*)d_in[9];
    const float* r1_pb = (const float*)d_in[10];
    const float* r1_lw = (const float*)d_in[11];
    const float* r1_lb = (const float*)d_in[12];
    const float* r1_ow = (const float*)d_in[13];
    const float* r1_ob = (const float*)d_in[14];
    const float* r2_pw = (const float*)d_in[15];
    const float* r2_pb = (const float*)d_in[16];
    const float* r2_lw = (const float*)d_in[17];
    const float* r2_lb = (const float*)d_in[18];
    const float* r2_ow = (const float*)d_in[19];
    const float* r2_ob = (const float*)d_in[20];
    float* out = (float*)d_out;

    cudaFuncSetAttribute(gemm_uv_kernel,  cudaFuncAttributeMaxDynamicSharedMemorySize, GEMM_SMEM);
    cudaFuncSetAttribute(gemm_out_kernel, cudaFuncAttributeMaxDynamicSharedMemorySize, GOUT_SMEM);
    cudaFuncSetAttribute(conv_kernel,     cudaFuncAttributeMaxDynamicSharedMemorySize, CONV_SMEM);
    cudaFuncSetAttribute(rpe_gemm,        cudaFuncAttributeMaxDynamicSharedMemorySize, RG_SMEM);

    cvt_kernel <<<1152, 256>>>(Wu, Wv, Wo);                                      // 0
    norm_kernel<<<4096, 256>>>(x);                                               // 1
    rpe_norm<<<32, 256>>>(r1_pw, r1_pb, r2_pw, r2_pb, r1_lb, r2_lb, 0, 1);       // 2: X0 -> rB
    gemm_uv_kernel<<<dim3(TOK / 128, D1 / 128, 2), 128, GEMM_SMEM>>>(bu, bv);    // 3 (profiled)
    rpe_gemm<<<dim3(8, 4, 2), 256, RG_SMEM>>>(r1_lw, r2_lw, 0, RPEW);            // 4: layer0
    rpe_norm<<<32, 256>>>(r1_pw, r1_pb, r2_pw, r2_pb, r1_lb, r2_lb, 0, 0);       // 5
    rpe_gemm<<<dim3(8, 4, 2), 256, RG_SMEM>>>(r1_lw, r2_lw, RPEW * RPEW, RPEW);  // 6: layer1
    rpe_norm<<<32, 256>>>(r1_pw, r1_pb, r2_pw, r2_pb, r1_lb, r2_lb, RPEW, 0);    // 7
    rpe_gemm<<<dim3(8, 4, 2), 256, RG_SMEM>>>(r1_lw, r2_lw, 2 * RPEW * RPEW, RPEW); // 8: layer2
    rpe_norm<<<32, 256>>>(r1_pw, r1_pb, r2_pw, r2_pb, r1_lb, r2_lb, 2 * RPEW, 0);// 9
    rpe_gemm<<<dim3(12, 4, 2), 256, RG_SMEM>>>(r1_ow, r2_ow, 0, D1);             // 10: final
    toep_kernel<<<D1, 256>>>(r1_ob, r2_ob);                                      // 11: reduce+tables

    conv_kernel<<<dim3(D1 / 2, BSZ), 256, CONV_SMEM>>>();                        // 12
    gemm_out_kernel<<<dim3(TOK / 128, EDIM / 128), 128, GOUT_SMEM>>>(x, bo, out);// 13
}

// round 16
// speedup vs baseline: 1.3141x; 1.0010x over previous
#include <cuda_runtime.h>
#include <cuda_bf16.h>
#include <mma.h>
#include <math.h>
#include <stdint.h>

using namespace nvcuda;

// ---------------- problem constants ----------------
#define TOK   32768            // B*H*W
#define EDIM  384
#define D1    768
#define BSZ   8
#define NSP   64               // H = W = 64
#define RPEW  512
#define RP_SL 98304            // 128*768 floats per k-slice
#define RP_NET (4 * RP_SL)     // per-net partial block

// ---------------- device scratch (allocation-free) ----------------
__device__ __align__(256) __nv_bfloat16 g_xnb[(size_t)TOK * EDIM];   // normed x, bf16
__device__ __align__(256) __nv_bfloat16 g_ut [(size_t)D1 * TOK];     // u transposed [c][tok]
__device__ __align__(256) __nv_bfloat16 g_vt [(size_t)D1 * TOK];     // v transposed [c][tok]
__device__ __align__(256) __nv_bfloat16 g_gt [(size_t)D1 * TOK];     // g = u*tno, [c][tok]
__device__ __align__(256) __nv_bfloat16 g_wub[EDIM * D1];            // Wu [k][n]
__device__ __align__(256) __nv_bfloat16 g_wvb[EDIM * D1];            // Wv [k][n]
__device__ __align__(256) __nv_bfloat16 g_wob[D1 * EDIM];            // Wo [k][n]
__device__ __align__(256) float         g_at1[D1 * 128];             // W-axis coeffs [c][lag]
__device__ __align__(256) float         g_at2[D1 * 128];             // H-axis coeffs [c][lag]
__device__ __align__(256) float         g_rP [2 * 4 * 128 * 768];    // split-K partials
__device__ __align__(256) float         g_rB [2 * 128 * RPEW];       // rpe normalized
__device__ __align__(256) __nv_bfloat16 g_T2b [(size_t)D1 * 64 * 64]; // T2[c][i][k]
__device__ __align__(256) __nv_bfloat16 g_T1tb[(size_t)D1 * 64 * 64]; // T1t[c][k][j]
__device__ unsigned g_sync;                                           // grid barrier (zero-init)

// ---------------- cp.async helpers ----------------
__device__ __forceinline__ void cpa16(void* dst, const void* src) {
    unsigned int s = (unsigned int)__cvta_generic_to_shared(dst);
    asm volatile("cp.async.cg.shared.global [%0], [%1], 16;\n" :: "r"(s), "l"(src));
}
#define CP_COMMIT()  asm volatile("cp.async.commit_group;\n" ::: "memory")
#define CP_WAIT0()   asm volatile("cp.async.wait_group 0;\n" ::: "memory")
#define CP_WAIT1()   asm volatile("cp.async.wait_group 1;\n" ::: "memory")

__device__ __forceinline__ float silu_fast(float v) {
    float th;
    asm("tanh.approx.f32 %0, %1;" : "=f"(th) : "f"(v * 0.5f));
    return 0.5f * v + 0.5f * v * th;             // v * sigmoid(v)
}

// ---------------- mega prep: norm | weight cvt | rpe layer-0 X0 --------------
// blocks [0,4096): srms(x) ; [4096,5248): cvt ; [5248,5280): rpe X0 -> g_rB
__global__ void mega_prep(const float* __restrict__ x,
                          const float* __restrict__ wu, const float* __restrict__ wv,
                          const float* __restrict__ wo,
                          const float* __restrict__ pw1, const float* __restrict__ pb1,
                          const float* __restrict__ pw2, const float* __restrict__ pb2) {
    int bid = blockIdx.x;
    int tid = threadIdx.x;
    if (bid < 4096) {                            // ---- SimpleRMSNorm ----
        int w    = (bid * 256 + tid) >> 5;
        int lane = tid & 31;
        const float* xr = x + (size_t)w * EDIM;
        float v[12], s = 0.f;
#pragma unroll
        for (int i = 0; i < 12; i++) { v[i] = xr[lane + 32 * i]; s += v[i] * v[i]; }
#pragma unroll
        for (int o = 16; o; o >>= 1) s += __shfl_xor_sync(0xffffffffu, s, o);
        float r = rsqrtf(s / (float)EDIM + 1e-6f);
        __nv_bfloat16* o = g_xnb + (size_t)w * EDIM;
#pragma unroll
        for (int i = 0; i < 12; i++) o[lane + 32 * i] = __float2bfloat16(v[i] * r);
    } else if (bid < 5248) {                     // ---- weight convert ----
        int i = (bid - 4096) * 256 + tid;
        if (i < EDIM * D1) {
            g_wub[i] = __float2bfloat16(wu[i]);
            g_wvb[i] = __float2bfloat16(wv[i]);
            g_wob[i] = __float2bfloat16(wo[i]);
        }
    } else {                                     // ---- rpe X0 = relu(srms(relu(p*pw+pb)))
        int wid = tid >> 5, lane = tid & 31;
        int g = (bid - 5248) * 8 + wid;          // 0..255
        int net = g >> 7, r = g & 127;
        const float* pw = net ? pw2 : pw1;
        const float* pb = net ? pb2 : pb1;
        float p = (r == 0 || r == 64) ? 0.f : (r < 64 ? (float)r : (float)(r - 128));
        float4 v[4];
#pragma unroll
        for (int i = 0; i < 4; i++) {
            float4 w4 = ((const float4*)pw)[lane + 32 * i];
            float4 b4 = ((const float4*)pb)[lane + 32 * i];
            v[i].x = fmaxf(p * w4.x + b4.x, 0.f);
            v[i].y = fmaxf(p * w4.y + b4.y, 0.f);
            v[i].z = fmaxf(p * w4.z + b4.z, 0.f);
            v[i].w = fmaxf(p * w4.w + b4.w, 0.f);
        }
        float ss = 0.f;
#pragma unroll
        for (int i = 0; i < 4; i++)
            ss += v[i].x * v[i].x + v[i].y * v[i].y + v[i].z * v[i].z + v[i].w * v[i].w;
#pragma unroll
        for (int o = 16; o; o >>= 1) ss += __shfl_xor_sync(0xffffffffu, ss, o);
        float rs = rsqrtf(ss / (float)RPEW + 1e-6f);
        float* Xo = g_rB + (size_t)net * 128 * RPEW + (size_t)r * RPEW;
#pragma unroll
        for (int i = 0; i < 4; i++) {
            float4 o4;
            o4.x = fmaxf(v[i].x * rs, 0.f); o4.y = fmaxf(v[i].y * rs, 0.f);
            o4.z = fmaxf(v[i].z * rs, 0.f); o4.w = fmaxf(v[i].w * rs, 0.f);
            ((float4*)Xo)[lane + 32 * i] = o4;
        }
    }
}

// ---------------- fused RPE chain: 3x(gemm+norm) + final gemm, 96 blocks -----
#define RX_LD 36
#define RX_STG (128 * RX_LD)         // 4608 floats / stage
#define RW_LD 68
#define RW_STG (32 * RW_LD)          // 2176 floats / stage
#define RG_SMEM (2 * RX_STG * 4 + 2 * RW_STG * 4)   // 54272 B
#define RF_NB 96

__device__ __forceinline__ void rpe_grid_bar(int phase) {
    __syncthreads();
    if (threadIdx.x == 0) {
        __threadfence();
        atomicAdd(&g_sync, 1u);
        while (*(volatile unsigned*)&g_sync < (unsigned)(phase * RF_NB)) {}
        __threadfence();
    }
    __syncthreads();
}

// One split-K TF32 GEMM tile: partial[ks] = g_rB[net][:,ks*128:+128] @ W -> g_rP
__device__ void rpe_layer_tile(const float* __restrict__ W, int N,
                               int net, int ks, int c0, char* sm, int tid) {
    float* Xs = (float*)sm;                         // 2 x [128][36]
    float* Ws = (float*)(sm + 2 * RX_STG * 4);      // 2 x [32][68]
    float* St = (float*)sm;                         // [128][68] alias
    const float* Xi = g_rB + (size_t)net * 128 * RPEW;
    int kbase = ks * 128;
    int wid = tid >> 5;
    int wm = wid & 3, wn = wid >> 2;

    wmma::fragment<wmma::accumulator, 16, 16, 8, float> acc[2][2];
#pragma unroll
    for (int i = 0; i < 2; i++)
#pragma unroll
        for (int j = 0; j < 2; j++) wmma::fill_fragment(acc[i][j], 0.f);

#define RG_LOAD(k0, st)                                                              \
    {                                                                                \
        _Pragma("unroll")                                                            \
        for (int l = 0; l < 4; l++) {                                                \
            int a = tid + 256 * l;                                                   \
            int row = a >> 3, ch = a & 7;                                            \
            cpa16(Xs + (st) * RX_STG + row * RX_LD + ch * 4,                         \
                  Xi + (size_t)row * RPEW + kbase + (k0) + ch * 4);                  \
        }                                                                            \
        _Pragma("unroll")                                                            \
        for (int l = 0; l < 2; l++) {                                                \
            int a = tid + 256 * l;                                                   \
            int row = a >> 4, ch = a & 15;                                           \
            cpa16(Ws + (st) * RW_STG + row * RW_LD + ch * 4,                         \
                  W + (size_t)(kbase + (k0) + row) * N + c0 + ch * 4);               \
        }                                                                            \
        CP_COMMIT();                                                                 \
    }

    RG_LOAD(0, 0);
    const int NT = 4;
    for (int t = 0; t < NT; t++) {
        if (t + 1 < NT) { RG_LOAD((t + 1) * 32, (t + 1) & 1); CP_WAIT1(); }
        else           { CP_WAIT0(); }
        __syncthreads();
        const float* Xc = Xs + (t & 1) * RX_STG;
        const float* Wc = Ws + (t & 1) * RW_STG;
#pragma unroll
        for (int kk = 0; kk < 32; kk += 8) {
            wmma::fragment<wmma::matrix_a, 16, 16, 8, wmma::precision::tf32, wmma::row_major> af[2];
            wmma::fragment<wmma::matrix_b, 16, 16, 8, wmma::precision::tf32, wmma::row_major> bf[2];
#pragma unroll
            for (int i = 0; i < 2; i++) {
                wmma::load_matrix_sync(af[i], Xc + (wm * 32 + 16 * i) * RX_LD + kk, RX_LD);
#pragma unroll
                for (int e = 0; e < af[i].num_elements; e++)
                    af[i].x[e] = wmma::__float_to_tf32(af[i].x[e]);
            }
#pragma unroll
            for (int j = 0; j < 2; j++) {
                wmma::load_matrix_sync(bf[j], Wc + kk * RW_LD + wn * 32 + 16 * j, RW_LD);
#pragma unroll
                for (int e = 0; e < bf[j].num_elements; e++)
                    bf[j].x[e] = wmma::__float_to_tf32(bf[j].x[e]);
            }
#pragma unroll
            for (int i = 0; i < 2; i++)
#pragma unroll
                for (int j = 0; j < 2; j++) wmma::mma_sync(acc[i][j], af[i], bf[j], acc[i][j]);
        }
        __syncthreads();
    }
#pragma unroll
    for (int i = 0; i < 2; i++)
#pragma unroll
        for (int j = 0; j < 2; j++)
            wmma::store_matrix_sync(St + (wm * 32 + 16 * i) * RW_LD + wn * 32 + 16 * j,
                                    acc[i][j], RW_LD, wmma::mem_row_major);
    __syncthreads();
    float* Po = g_rP + (size_t)net * RP_NET + (size_t)ks * RP_SL;
#pragma unroll
    for (int l = 0; l < 32; l++) {
        int a = tid + 256 * l;
        int r = a >> 6, c = a & 63;
        Po[(size_t)r * 768 + c0 + c] = St[r * RW_LD + c];
    }
    __syncthreads();
#undef RG_LOAD
}

// Norm phase: blocks 0..31, warp per row: g_rB = relu(srms(reduce(g_rP)+bias))
__device__ void rpe_norm_phase(int b, const float* __restrict__ lb1,
                               const float* __restrict__ lb2, int boff, int tid) {
    int wid = tid >> 5, lane = tid & 31;
    int g = b * 8 + wid;                         // 0..255
    int net = g >> 7, r = g & 127;
    const float* P  = g_rP + (size_t)net * RP_NET + (size_t)r * 768;
    const float* Bb = (net ? lb2 : lb1) + boff;
    float4 v[4];
#pragma unroll
    for (int i = 0; i < 4; i++) {
        int q = lane + 32 * i;
        float4 p0 = ((const float4*)(P + 0 * RP_SL))[q];
        float4 p1 = ((const float4*)(P + 1 * RP_SL))[q];
        float4 p2 = ((const float4*)(P + 2 * RP_SL))[q];
        float4 p3 = ((const float4*)(P + 3 * RP_SL))[q];
        float4 b4 = ((const float4*)Bb)[q];
        v[i].x = p0.x + p1.x + p2.x + p3.x + b4.x;
        v[i].y = p0.y + p1.y + p2.y + p3.y + b4.y;
        v[i].z = p0.z + p1.z + p2.z + p3.z + b4.z;
        v[i].w = p0.w + p1.w + p2.w + p3.w + b4.w;
    }
    float ss = 0.f;
#pragma unroll
    for (int i = 0; i < 4; i++)
        ss += v[i].x * v[i].x + v[i].y * v[i].y + v[i].z * v[i].z + v[i].w * v[i].w;
#pragma unroll
    for (int o = 16; o; o >>= 1) ss += __shfl_xor_sync(0xffffffffu, ss, o);
    float rs = rsqrtf(ss / (float)RPEW + 1e-6f);
    float* Xo = g_rB + (size_t)net * 128 * RPEW + (size_t)r * RPEW;
#pragma unroll
    for (int i = 0; i < 4; i++) {
        float4 o4;
        o4.x = fmaxf(v[i].x * rs, 0.f); o4.y = fmaxf(v[i].y * rs, 0.f);
        o4.z = fmaxf(v[i].z * rs, 0.f); o4.w = fmaxf(v[i].w * rs, 0.f);
        ((float4*)Xo)[lane + 32 * i] = o4;
    }
}

__global__ void __launch_bounds__(256)
rpe_fused(const float* __restrict__ lw1, const float* __restrict__ lb1,
          const float* __restrict__ lw2, const float* __restrict__ lb2,
          const float* __restrict__ ow1, const float* __restrict__ ow2) {
    extern __shared__ char sm[];
    int b = blockIdx.x;
    int tid = threadIdx.x;
    // 3 hidden layers: gemm (blocks 0..63) -> bar -> norm (blocks 0..31) -> bar
    for (int layer = 0; layer < 3; layer++) {
        if (b < 64) {
            int net = b >> 5, ks = (b >> 3) & 3, c0 = (b & 7) * 64;
            const float* W = (net ? lw2 : lw1) + (size_t)layer * RPEW * RPEW;
            rpe_layer_tile(W, RPEW, net, ks, c0, sm, tid);
        }
        rpe_grid_bar(2 * layer + 1);
        if (b < 32) rpe_norm_phase(b, lb1, lb2, layer * RPEW, tid);
        rpe_grid_bar(2 * layer + 2);
    }
    // final layer: all 96 blocks (12 c-tiles x 4 ks x 2 nets) -> g_rP
    {
        int net = b / 48, rem = b % 48;
        int ks = rem / 12, c0 = (rem % 12) * 64;
        const float* W = net ? ow2 : ow1;
        rpe_layer_tile(W, D1, net, ks, c0, sm, tid);
    }
    // self-resetting finish (no spin): last arriver zeroes the counter
    __syncthreads();
    if (tid == 0) {
        __threadfence();
        unsigned d = atomicAdd(&g_sync, 1u);
        if (d == (unsigned)(RF_NB * 7) - 1u) g_sync = 0u;
    }
}

// ---------------- GEMM: u/v = silu(xn @ W + b), 128x128 tile -----------------
#define GA_LD 72
#define GB_LD 136
#define GS_LD 132
#define A_STG (128 * GA_LD)          // elems per A stage
#define B_STG (64 * GB_LD)
#define GEMM_SMEM ((3 * A_STG + 3 * B_STG) * 2)   // 107520 B; St (67568) aliases

__global__ void __launch_bounds__(128, 2)
gemm_uv_kernel(const float* __restrict__ bu, const float* __restrict__ bv) {
    extern __shared__ char smem[];
    __nv_bfloat16* As = (__nv_bfloat16*)smem;                         // 3 x 128x72
    __nv_bfloat16* Bs = (__nv_bfloat16*)(smem + 3 * A_STG * 2);       // 3 x 64x136
    float*         St = (float*)smem;                                  // [128ch][132] alias

    int m0 = blockIdx.x * 128;
    int n0 = blockIdx.y * 128;
    int mode = blockIdx.z;                                             // 0:u 1:v
    const __nv_bfloat16* W = mode ? g_wvb : g_wub;
    const float* bias = mode ? bv : bu;

    int tid = threadIdx.x;                       // 0..127
    int wid = tid >> 5;                          // 0..3
    int wm = wid & 1, wn = wid >> 1;             // 2x2 warp grid, 64x64 each

    wmma::fragment<wmma::accumulator, 16, 16, 16, float> acc[4][4];
#pragma unroll
    for (int i = 0; i < 4; i++)
#pragma unroll
        for (int j = 0; j < 4; j++) wmma::fill_fragment(acc[i][j], 0.f);

#define UV_LOAD(k0, st)                                                              \
    {                                                                                \
        _Pragma("unroll")                                                            \
        for (int l = 0; l < 8; l++) {            /* A: 128 rows x 8 chunks */        \
            int a = tid + 128 * l;                                                   \
            int row = a >> 3, ch = a & 7;                                            \
            cpa16(As + (st) * A_STG + row * GA_LD + ch * 8,                          \
                  g_xnb + (size_t)(m0 + row) * EDIM + (k0) + ch * 8);                \
        }                                                                            \
        _Pragma("unroll")                                                            \
        for (int l = 0; l < 8; l++) {            /* B: 64 rows x 16 chunks */        \
            int a = tid + 128 * l;                                                   \
            int row = a >> 4, ch = a & 15;                                           \
            cpa16(Bs + (st) * B_STG + row * GB_LD + ch * 8,                          \
                  W + (size_t)((k0) + row) * D1 + n0 + ch * 8);                      \
        }                                                                            \
        CP_COMMIT();                                                                 \
    }

    UV_LOAD(0, 0);
    UV_LOAD(64, 1);
    const int NT = EDIM / 64;                    // 6
    for (int t = 0; t < NT; t++) {
        if (t + 1 < NT) CP_WAIT1(); else CP_WAIT0();
        __syncthreads();                         // single barrier per iter
        if (t + 2 < NT) UV_LOAD((t + 2) * 64, (t + 2) % 3);
        const __nv_bfloat16* Ac = As + (t % 3) * A_STG;
        const __nv_bfloat16* Bc = Bs + (t % 3) * B_STG;
#pragma unroll
        for (int kk = 0; kk < 64; kk += 16) {
            wmma::fragment<wmma::matrix_a, 16, 16, 16, __nv_bfloat16, wmma::row_major> af[4];
            wmma::fragment<wmma::matrix_b, 16, 16, 16, __nv_bfloat16, wmma::row_major> bf[4];
#pragma unroll
            for (int i = 0; i < 4; i++)
                wmma::load_matrix_sync(af[i], Ac + (wm * 64 + 16 * i) * GA_LD + kk, GA_LD);
#pragma unroll
            for (int j = 0; j < 4; j++)
                wmma::load_matrix_sync(bf[j], Bc + kk * GB_LD + wn * 64 + 16 * j, GB_LD);
#pragma unroll
            for (int i = 0; i < 4; i++)
#pragma unroll
                for (int j = 0; j < 4; j++) wmma::mma_sync(acc[i][j], af[i], bf[j], acc[i][j]);
        }
    }
    __syncthreads();                             // all compute done before St alias
    // col-major store: element (tok i, ch j) -> St[j * GS_LD + i]
#pragma unroll
    for (int i = 0; i < 4; i++)
#pragma unroll
        for (int j = 0; j < 4; j++)
            wmma::store_matrix_sync(St + (wm * 64 + 16 * i) + (size_t)(wn * 64 + 16 * j) * GS_LD,
                                    acc[i][j], GS_LD, wmma::mem_col_major);
    __syncthreads();
    // silu + transposed write: [c][tok], bf16, float4 reads / 8B stores
    {
        int lane = tid & 31;
        int wrp  = tid >> 5;
        __nv_bfloat16* dst = mode ? g_vt : g_ut;
#pragma unroll
        for (int l = 0; l < 32; l++) {
            int j = l * 4 + wrp;                 // channel 0..127
            float4 v4 = *(const float4*)(St + (size_t)j * GS_LD + lane * 4);
            float b = bias[n0 + j];
            float s0 = silu_fast(v4.x + b), s1 = silu_fast(v4.y + b);
            float s2 = silu_fast(v4.z + b), s3 = silu_fast(v4.w + b);
            __nv_bfloat162 h0 = __floats2bfloat162_rn(s0, s1);
            __nv_bfloat162 h1 = __floats2bfloat162_rn(s2, s3);
            uint2 pk;
            pk.x = *(unsigned int*)&h0;
            pk.y = *(unsigned int*)&h1;
            *(uint2*)(dst + (size_t)(n0 + j) * TOK + m0 + lane * 4) = pk;
        }
    }
#undef UV_LOAD
}

// ---------------- Toeplitz tables: reduce final partials + bias + build ------
__global__ void toep_kernel(const float* __restrict__ ob1, const float* __restrict__ ob2) {
    __shared__ float a1[128], a2[128];
    int c = blockIdx.x;
    int tid = threadIdx.x;
    if (tid < 128) {
        const float* P1 = g_rP + (size_t)tid * 768 + c;            // net 0 (r1, W-axis)
        const float* P2 = g_rP + RP_NET + (size_t)tid * 768 + c;   // net 1 (r2, H-axis)
        a1[tid] = P1[0] + P1[RP_SL] + P1[2 * RP_SL] + P1[3 * RP_SL] + ob1[c];
        a2[tid] = P2[0] + P2[RP_SL] + P2[2 * RP_SL] + P2[3 * RP_SL] + ob2[c];
        g_at1[(size_t)c * 128 + tid] = a1[tid];
        g_at2[(size_t)c * 128 + tid] = a2[tid];
    }
    __syncthreads();
#pragma unroll
    for (int l = 0; l < 16; l++) {
        int idx = tid + 256 * l;                 // 0..4095
        int r = idx >> 6, s = idx & 63;
        g_T2b [(size_t)c * 4096 + idx] = __float2bfloat16(a2[(r - s) & 127]);  // T2[i][k]
        g_T1tb[(size_t)c * 4096 + idx] = __float2bfloat16(a1[(s - r) & 127]);  // T1t[k][j]
    }
}

// ---------------- TNO conv: 2 channels x 1 batch per block, cp.async loads ----
#define CT_LD 72
#define CT_CH 4608            // 64*72 elems per channel tile
#define CONV_SMEM 55296       // T2(18432) + T1t(18432) + V(18432); St aliases T2+T1t

__global__ void conv_kernel() {
    extern __shared__ char sm[];
    __nv_bfloat16* T2s = (__nv_bfloat16*)(sm);
    __nv_bfloat16* T1s = (__nv_bfloat16*)(sm + 18432);
    __nv_bfloat16* Vs  = (__nv_bfloat16*)(sm + 36864);
    float*         St  = (float*)sm;                    // 2*64*72*4 = 36864 alias

    int c0 = blockIdx.x * 2;
    int b  = blockIdx.y;
    int tid = threadIdx.x;

#pragma unroll
    for (int l = 0; l < 4; l++) {                       // 1024 uint4 each tensor
        int a = tid + 256 * l;
        int cc = a >> 9, rq = a & 511;
        int r = rq >> 3, q = rq & 7;
        cpa16(T2s + cc * CT_CH + r * CT_LD + q * 8,
              g_T2b + (size_t)(c0 + cc) * 4096 + r * 64 + q * 8);
        cpa16(T1s + cc * CT_CH + r * CT_LD + q * 8,
              g_T1tb + (size_t)(c0 + cc) * 4096 + r * 64 + q * 8);
        cpa16(Vs + cc * CT_CH + r * CT_LD + q * 8,
              g_vt + (size_t)(c0 + cc) * TOK + b * 4096 + r * 64 + q * 8);
    }
    CP_COMMIT();
    CP_WAIT0();
    __syncthreads();

    int wid = tid >> 5;
    int cc  = wid >> 2;                                 // 2 channels, 4 warps each
    int r0  = (wid & 3) * 16;                           // 16 rows per warp
    __nv_bfloat16* Vc  = Vs  + cc * CT_CH;
    __nv_bfloat16* T2c = T2s + cc * CT_CH;
    __nv_bfloat16* T1c = T1s + cc * CT_CH;

    wmma::fragment<wmma::accumulator, 16, 16, 16, float> acc[4];
#pragma unroll
    for (int j = 0; j < 4; j++) wmma::fill_fragment(acc[j], 0.f);

#pragma unroll
    for (int kt = 0; kt < 4; kt++) {
        wmma::fragment<wmma::matrix_a, 16, 16, 16, __nv_bfloat16, wmma::row_major> af;
        wmma::fragment<wmma::matrix_b, 16, 16, 16, __nv_bfloat16, wmma::row_major> bf[4];
        // product 1: T2 @ V
        wmma::load_matrix_sync(af, T2c + r0 * CT_LD + kt * 16, CT_LD);
#pragma unroll
        for (int j = 0; j < 4; j++)
            wmma::load_matrix_sync(bf[j], Vc + kt * 16 * CT_LD + 16 * j, CT_LD);
#pragma unroll
        for (int j = 0; j < 4; j++) wmma::mma_sync(acc[j], af, bf[j], acc[j]);
        // product 2: V @ T1t
        wmma::load_matrix_sync(af, Vc + r0 * CT_LD + kt * 16, CT_LD);
#pragma unroll
        for (int j = 0; j < 4; j++)
            wmma::load_matrix_sync(bf[j], T1c + kt * 16 * CT_LD + 16 * j, CT_LD);
#pragma unroll
        for (int j = 0; j < 4; j++) wmma::mma_sync(acc[j], af, bf[j], acc[j]);
    }
    __syncthreads();                                    // before aliasing T with St
#pragma unroll
    for (int j = 0; j < 4; j++)
        wmma::store_matrix_sync(St + cc * CT_CH + r0 * CT_LD + 16 * j,
                                acc[j], CT_LD, wmma::mem_row_major);
    __syncthreads();
#pragma unroll 4
    for (int l = 0; l < 32; l++) {                      // g = u * tno -> bf16
        int a = tid + 256 * l;                          // 0..8191
        int cc2 = a >> 12, hw = a & 4095;
        int h = hw >> 6, w = hw & 63;
        float t = St[cc2 * CT_CH + h * CT_LD + w];
        float u = __bfloat162float(g_ut[(size_t)(c0 + cc2) * TOK + b * 4096 + hw]);
        g_gt[(size_t)(c0 + cc2) * TOK + b * 4096 + hw] = __float2bfloat16(t * u);
    }
}

// ---------------- final GEMM: out = g @ Wo + bo + x --------------------------
#define GSO_LD 132
#define GO_LD 136
#define O_STG (64 * GO_LD)
#define GOUT_SMEM (6 * O_STG * 2)     // 104448 B; St (128x132 f32 = 67584) aliases

__global__ void __launch_bounds__(128, 2)
gemm_out_kernel(const float* __restrict__ x, const float* __restrict__ bo,
                float* __restrict__ out) {
    extern __shared__ char smem[];
    __nv_bfloat16* As = (__nv_bfloat16*)smem;                     // 3 x [64][136]
    __nv_bfloat16* Bs = (__nv_bfloat16*)(smem + 3 * O_STG * 2);   // 3 x [64][136]
    float*         St = (float*)smem;                              // 128x132 alias

    int m0 = blockIdx.x * 128;
    int n0 = blockIdx.y * 128;
    int tid = threadIdx.x;                       // 0..127
    int wid = tid >> 5;                          // 0..3
    int wm = wid & 1, wn = wid >> 1;             // 2x2 warp grid, 64x64 each

    wmma::fragment<wmma::accumulator, 16, 16, 16, float> acc[4][4];
#pragma unroll
    for (int i = 0; i < 4; i++)
#pragma unroll
        for (int j = 0; j < 4; j++) wmma::fill_fragment(acc[i][j], 0.f);

#define GO_LOAD(k0, st)                                                              \
    {                                                                                \
        _Pragma("unroll")                                                            \
        for (int l = 0; l < 8; l++) {            /* A: 64 k-rows x 16 m-chunks */    \
            int a = tid + 128 * l;                                                   \
            int row = a >> 4, ch = a & 15;                                           \
            cpa16(As + (st) * O_STG + row * GO_LD + ch * 8,                          \
                  g_gt + (size_t)((k0) + row) * TOK + m0 + ch * 8);                  \
        }                                                                            \
        _Pragma("unroll")                                                            \
        for (int l = 0; l < 8; l++) {            /* B: 64 k-rows x 16 n-chunks */    \
            int a = tid + 128 * l;                                                   \
            int row = a >> 4, ch = a & 15;                                           \
            cpa16(Bs + (st) * O_STG + row * GO_LD + ch * 8,                          \
                  g_wob + (size_t)((k0) + row) * EDIM + n0 + ch * 8);                \
        }                                                                            \
        CP_COMMIT();                                                                 \
    }

    GO_LOAD(0, 0);
    GO_LOAD(64, 1);
    const int NT = D1 / 64;                      // 12
    for (int t = 0; t < NT; t++) {
        if (t + 1 < NT) CP_WAIT1(); else CP_WAIT0();
        __syncthreads();                         // single barrier per iter
        if (t + 2 < NT) GO_LOAD((t + 2) * 64, (t + 2) % 3);
        const __nv_bfloat16* Ac = As + (t % 3) * O_STG;
        const __nv_bfloat16* Bc = Bs + (t % 3) * O_STG;
#pragma unroll
        for (int kk = 0; kk < 64; kk += 16) {
            wmma::fragment<wmma::matrix_a, 16, 16, 16, __nv_bfloat16, wmma::col_major> af[4];
            wmma::fragment<wmma::matrix_b, 16, 16, 16, __nv_bfloat16, wmma::row_major> bf[4];
#pragma unroll
            for (int i = 0; i < 4; i++)
                wmma::load_matrix_sync(af[i], Ac + kk * GO_LD + wm * 64 + 16 * i, GO_LD);
#pragma unroll
            for (int j = 0; j < 4; j++)
                wmma::load_matrix_sync(bf[j], Bc + kk * GO_LD + wn * 64 + 16 * j, GO_LD);
#pragma unroll
            for (int i = 0; i < 4; i++)
#pragma unroll
                for (int j = 0; j < 4; j++) wmma::mma_sync(acc[i][j], af[i], bf[j], acc[i][j]);
        }
    }
    __syncthreads();                             // all compute done before St alias
#pragma unroll
    for (int i = 0; i < 4; i++)
#pragma unroll
        for (int j = 0; j < 4; j++)
            wmma::store_matrix_sync(St + (wm * 64 + 16 * i) * GSO_LD + wn * 64 + 16 * j,
                                    acc[i][j], GSO_LD, wmma::mem_row_major);
    __syncthreads();
    // float4 epilogue: 128 rows x 32 float4 cols
#pragma unroll
    for (int l = 0; l < 32; l++) {
        int a = tid + 128 * l;                   // 0..4095
        int i = a >> 5, jq = a & 31;             // row, float4-col
        float4 s4 = *(const float4*)(St + (size_t)i * GSO_LD + jq * 4);
        float4 b4 = *(const float4*)(bo + n0 + jq * 4);
        size_t go = (size_t)(m0 + i) * EDIM + n0 + jq * 4;
        float4 x4 = *(const float4*)(x + go);
        float4 o4;
        o4.x = s4.x + b4.x + x4.x;
        o4.y = s4.y + b4.y + x4.y;
        o4.z = s4.z + b4.z + x4.z;
        o4.w = s4.w + b4.w + x4.w;
        *(float4*)(out + go) = o4;
    }
#undef GO_LOAD
}

// ---------------- launch ------------------------------------------------------
extern "C" void kernel_launch(void* const* d_in, const int* in_sizes, int n_in,
                              void* d_out, int out_size) {
    (void)in_sizes; (void)n_in; (void)out_size;
    const float* x     = (const float*)d_in[0];
    const float* Wu    = (const float*)d_in[3];
    const float* bu    = (const float*)d_in[4];
    const float* Wv    = (const float*)d_in[5];
    const float* bv    = (const float*)d_in[6];
    const float* Wo    = (const float*)d_in[7];
    const float* bo    = (const float*)d_in[8];
    const float* r1_pw = (const float*)d_in[9];
    const float* r1_pb = (const float*)d_in[10];
    const float* r1_lw = (const float*)d_in[11];
    const float* r1_lb = (const float*)d_in[12];
    const float* r1_ow = (const float*)d_in[13];
    const float* r1_ob = (const float*)d_in[14];
    const float* r2_pw = (const float*)d_in[15];
    const float* r2_pb = (const float*)d_in[16];
    const float* r2_lw = (const float*)d_in[17];
    const float* r2_lb = (const float*)d_in[18];
    const float* r2_ow = (const float*)d_in[19];
    const float* r2_ob = (const float*)d_in[20];
    float* out = (float*)d_out;

    cudaFuncSetAttribute(gemm_uv_kernel,  cudaFuncAttributeMaxDynamicSharedMemorySize, GEMM_SMEM);
    cudaFuncSetAttribute(gemm_out_kernel, cudaFuncAttributeMaxDynamicSharedMemorySize, GOUT_SMEM);
    cudaFuncSetAttribute(conv_kernel,     cudaFuncAttributeMaxDynamicSharedMemorySize, CONV_SMEM);
    cudaFuncSetAttribute(rpe_fused,       cudaFuncAttributeMaxDynamicSharedMemorySize, RG_SMEM);

    mega_prep<<<5280, 256>>>(x, Wu, Wv, Wo, r1_pw, r1_pb, r2_pw, r2_pb);         // 0
    rpe_fused<<<RF_NB, 256, RG_SMEM>>>(r1_lw, r1_lb, r2_lw, r2_lb, r1_ow, r2_ow);// 1
    toep_kernel<<<D1, 256>>>(r1_ob, r2_ob);                                      // 2
    gemm_uv_kernel<<<dim3(TOK / 128, D1 / 128, 2), 128, GEMM_SMEM>>>(bu, bv);    // 3 (profiled)
    conv_kernel<<<dim3(D1 / 2, BSZ), 256, CONV_SMEM>>>();                        // 4
    gemm_out_kernel<<<dim3(TOK / 128, EDIM / 128), 128, GOUT_SMEM>>>(x, bo, out);// 5
}